// round 2
// baseline (speedup 1.0000x reference)
#include <cuda_runtime.h>
#include <cuda_bf16.h>
#include <math.h>

#define NN 50000
#define EE 800000
#define RR 8
#define IND 128
#define HID 64
#define OUTD 40

// ---------------- scratch (no allocations allowed -> device globals) --------
__device__ float    g_H[(size_t)NN * 512];    // [N, 8*64] per-relation projections
__device__ float    g_h1[(size_t)NN * HID];
__device__ float    g_h2[(size_t)NN * HID];
__device__ int      g_deg[NN];
__device__ int      g_indptr[NN + 1];
__device__ int      g_cursor[NN];
__device__ unsigned g_packed[EE];             // (rel<<16)|src, sorted by dst
__device__ int      g_is64_idx;               // edge_index stored as int64?
__device__ int      g_is64_typ;               // edge_type stored as int64?

// ---------------- dtype detection -------------------------------------------
// For int64 data with values < 2^31, every odd 32-bit word is 0. For int32
// random data the odds of 64 consecutive odd words all being 0 are ~0.
__global__ void detect_kernel(const unsigned* __restrict__ idx,
                              const unsigned* __restrict__ typ) {
    unsigned a = 0, b = 0;
    #pragma unroll
    for (int i = 0; i < 64; i++) { a |= idx[2 * i + 1]; b |= typ[2 * i + 1]; }
    g_is64_idx = (a == 0);
    g_is64_typ = (b == 0);
}

__device__ __forceinline__ int load_src(const void* ei, int e) {
    return g_is64_idx ? (int)((const long long*)ei)[e] : ((const int*)ei)[e];
}
__device__ __forceinline__ int load_dst(const void* ei, int e) {
    return g_is64_idx ? (int)((const long long*)ei)[EE + e] : ((const int*)ei)[EE + e];
}
__device__ __forceinline__ int load_rel(const void* et, int e) {
    return g_is64_typ ? (int)((const long long*)et)[e] : ((const int*)et)[e];
}

// ---------------- CSR build --------------------------------------------------
__global__ void zero_deg_kernel() {
    int i = blockIdx.x * blockDim.x + threadIdx.x;
    if (i < NN) g_deg[i] = 0;
}

__global__ void hist_kernel(const void* __restrict__ ei) {
    int e = blockIdx.x * blockDim.x + threadIdx.x;
    if (e >= EE) return;
    int dst = load_dst(ei, e);
    if ((unsigned)dst < NN) atomicAdd(&g_deg[dst], 1);
}

__global__ void scan_kernel() {
    __shared__ int wsum[32];
    __shared__ int carry;
    int t = threadIdx.x, lane = t & 31, wid = t >> 5;
    if (t == 0) carry = 0;
    __syncthreads();
    for (int base = 0; base < NN; base += 1024) {
        int i = base + t;
        int v = (i < NN) ? g_deg[i] : 0;
        int x = v;
        #pragma unroll
        for (int o = 1; o < 32; o <<= 1) {
            int y = __shfl_up_sync(0xffffffffu, x, o);
            if (lane >= o) x += y;
        }
        if (lane == 31) wsum[wid] = x;
        __syncthreads();
        if (wid == 0) {
            int s = wsum[lane];
            #pragma unroll
            for (int o = 1; o < 32; o <<= 1) {
                int y = __shfl_up_sync(0xffffffffu, s, o);
                if (lane >= o) s += y;
            }
            wsum[lane] = s;
        }
        __syncthreads();
        int woff = (wid > 0) ? wsum[wid - 1] : 0;
        int excl = carry + woff + x - v;
        if (i < NN) { g_indptr[i] = excl; g_cursor[i] = excl; }
        __syncthreads();
        if (t == 0) carry += wsum[31];
        __syncthreads();
    }
    if (t == 0) g_indptr[NN] = carry;
}

__global__ void scatter_kernel(const void* __restrict__ ei,
                               const void* __restrict__ et) {
    int e = blockIdx.x * blockDim.x + threadIdx.x;
    if (e >= EE) return;
    int src = load_src(ei, e);
    int dst = load_dst(ei, e);
    int rel = load_rel(et, e);
    if ((unsigned)src >= NN || (unsigned)dst >= NN || (unsigned)rel >= RR) return;
    int pos = atomicAdd(&g_cursor[dst], 1);
    if ((unsigned)pos < EE) g_packed[pos] = ((unsigned)rel << 16) | (unsigned)src;
}

// ---------------- GEMM: C[m, c0 + 64cols] = A[m,:K] @ W[rel][:K][:64] -------
template <int K>
__global__ void __launch_bounds__(256)
gemm_kernel(const float* __restrict__ Ain, const float* __restrict__ W,
            const float* __restrict__ bias, int aSel, int cSel) {
    __shared__ float As[16][132];
    __shared__ float Bs[16][64];

    const float* A = aSel ? g_h1 : Ain;
    int tid = threadIdx.x;
    int m0  = blockIdx.x * 128;
    int rel = blockIdx.y;
    const float* Wr = W + (size_t)rel * K * 64;

    float* C; int ldc, c0;
    if (cSel == 0)      { C = g_H;  ldc = 512; c0 = rel * 64; }
    else if (cSel == 1) { C = g_h1; ldc = 64;  c0 = 0; }
    else                { C = g_h2; ldc = 64;  c0 = 0; }

    float acc[8][4];
    #pragma unroll
    for (int i = 0; i < 8; i++)
        #pragma unroll
        for (int j = 0; j < 4; j++) acc[i][j] = 0.f;

    int ar = tid >> 2;            // 0..63 (two row passes: ar, ar+64)
    int ak = (tid & 3) * 4;       // k sub-chunk
    int ty = tid >> 4, tx = tid & 15;

    for (int kt = 0; kt < K; kt += 16) {
        #pragma unroll
        for (int s = 0; s < 2; s++) {
            int row = m0 + ar + s * 64;
            float4 v = make_float4(0.f, 0.f, 0.f, 0.f);
            if (row < NN) v = *(const float4*)&A[(size_t)row * K + kt + ak];
            As[ak + 0][ar + s * 64] = v.x;
            As[ak + 1][ar + s * 64] = v.y;
            As[ak + 2][ar + s * 64] = v.z;
            As[ak + 3][ar + s * 64] = v.w;
        }
        {
            float4 v = *(const float4*)&Wr[(size_t)(kt + (tid >> 4)) * 64 + (tid & 15) * 4];
            *(float4*)&Bs[tid >> 4][(tid & 15) * 4] = v;
        }
        __syncthreads();
        #pragma unroll
        for (int k = 0; k < 16; k++) {
            float4 a0 = *(const float4*)&As[k][ty * 8];
            float4 a1 = *(const float4*)&As[k][ty * 8 + 4];
            float4 b  = *(const float4*)&Bs[k][tx * 4];
            float a[8] = {a0.x, a0.y, a0.z, a0.w, a1.x, a1.y, a1.z, a1.w};
            float bb[4] = {b.x, b.y, b.z, b.w};
            #pragma unroll
            for (int i = 0; i < 8; i++)
                #pragma unroll
                for (int j = 0; j < 4; j++) acc[i][j] += a[i] * bb[j];
        }
        __syncthreads();
    }

    #pragma unroll
    for (int i = 0; i < 8; i++) {
        int row = m0 + ty * 8 + i;
        if (row < NN) {
            #pragma unroll
            for (int j = 0; j < 4; j++) {
                float v = acc[i][j];
                if (bias) v += bias[tx * 4 + j];
                C[(size_t)row * ldc + c0 + tx * 4 + j] = v;
            }
        }
    }
}

// ---------------- aggregation: one warp per dst node ------------------------
__global__ void agg_kernel(int sel) {
    int gw   = (blockIdx.x * blockDim.x + threadIdx.x) >> 5;
    int lane = threadIdx.x & 31;
    if (gw >= NN) return;
    float* h = (sel == 1) ? g_h1 : g_h2;
    int beg = g_indptr[gw], end = g_indptr[gw + 1];

    float acc[8][2];
    int   cnt[8];
    #pragma unroll
    for (int r = 0; r < 8; r++) { acc[r][0] = 0.f; acc[r][1] = 0.f; cnt[r] = 0; }

    for (int e = beg; e < end; e++) {
        unsigned p = g_packed[e];
        int rel = p >> 16;
        int src = p & 0xffff;
        float2 v = *(const float2*)&g_H[(size_t)src * 512 + rel * 64 + lane * 2];
        #pragma unroll
        for (int r = 0; r < 8; r++) {
            if (rel == r) { acc[r][0] += v.x; acc[r][1] += v.y; cnt[r]++; }
        }
    }

    float s0 = 0.f, s1 = 0.f;
    #pragma unroll
    for (int r = 0; r < 8; r++) {
        float inv = 1.f / (float)max(cnt[r], 1);
        s0 += acc[r][0] * inv;
        s1 += acc[r][1] * inv;
    }
    float2 base = *(const float2*)&h[(size_t)gw * 64 + lane * 2];
    float o0 = base.x + s0, o1 = base.y + s1;
    o0 = o0 > 0.f ? o0 : 0.f;
    o1 = o1 > 0.f ? o1 : 0.f;
    *(float2*)&h[(size_t)gw * 64 + lane * 2] = make_float2(o0, o1);
}

// ---------------- final: logits = h2 @ Wl + bl, then log_softmax ------------
__global__ void __launch_bounds__(256)
final_kernel(const float* __restrict__ Wl, const float* __restrict__ bl,
             float* __restrict__ out) {
    __shared__ float sW[64 * 40];
    __shared__ float sb[40];
    __shared__ float srow[8][64];
    int t = threadIdx.x;
    for (int i = t; i < 64 * 40; i += 256) sW[i] = Wl[i];
    if (t < 40) sb[t] = bl[t];
    __syncthreads();

    int warp = t >> 5, lane = t & 31;
    int n = blockIdx.x * 8 + warp;
    if (n < NN) {
        srow[warp][lane]      = g_h2[(size_t)n * 64 + lane];
        srow[warp][lane + 32] = g_h2[(size_t)n * 64 + 32 + lane];
    }
    __syncwarp();

    float v1 = -1e30f, v2 = -1e30f;
    if (n < NN) {
        float d = sb[lane];
        #pragma unroll
        for (int k = 0; k < 64; k++) d += srow[warp][k] * sW[k * 40 + lane];
        v1 = d;
        if (lane < 8) {
            float d2 = sb[lane + 32];
            #pragma unroll
            for (int k = 0; k < 64; k++) d2 += srow[warp][k] * sW[k * 40 + lane + 32];
            v2 = d2;
        }
    }
    float m = fmaxf(v1, v2);
    #pragma unroll
    for (int o = 16; o > 0; o >>= 1) m = fmaxf(m, __shfl_xor_sync(0xffffffffu, m, o));
    float e1 = __expf(v1 - m);
    float e2 = (lane < 8) ? __expf(v2 - m) : 0.f;
    float s = e1 + e2;
    #pragma unroll
    for (int o = 16; o > 0; o >>= 1) s += __shfl_xor_sync(0xffffffffu, s, o);
    float lse = m + __logf(s);
    if (n < NN) {
        out[(size_t)n * 40 + lane] = v1 - lse;
        if (lane < 8) out[(size_t)n * 40 + 32 + lane] = v2 - lse;
    }
}

// ---------------- launch -----------------------------------------------------
extern "C" void kernel_launch(void* const* d_in, const int* in_sizes, int n_in,
                              void* d_out, int out_size) {
    const float* x     = (const float*)d_in[0];
    const void*  ei    = d_in[1];
    const void*  et    = d_in[2];
    const float* W1    = (const float*)d_in[3];
    const float* root1 = (const float*)d_in[4];
    const float* b1    = (const float*)d_in[5];
    const float* W2    = (const float*)d_in[6];
    const float* root2 = (const float*)d_in[7];
    const float* b2    = (const float*)d_in[8];
    const float* Wl    = (const float*)d_in[9];
    const float* bl    = (const float*)d_in[10];
    float*       out   = (float*)d_out;

    // dtype sniff + CSR build (same edges for both layers)
    detect_kernel<<<1, 1>>>((const unsigned*)ei, (const unsigned*)et);
    zero_deg_kernel<<<(NN + 255) / 256, 256>>>();
    hist_kernel<<<(EE + 255) / 256, 256>>>(ei);
    scan_kernel<<<1, 1024>>>();
    scatter_kernel<<<(EE + 255) / 256, 256>>>(ei, et);

    dim3 gcat((NN + 127) / 128, 8);
    dim3 groot((NN + 127) / 128, 1);

    // layer 1
    gemm_kernel<128><<<gcat, 256>>>(x, W1, nullptr, 0, 0);     // g_H = x @ W1[r]
    gemm_kernel<128><<<groot, 256>>>(x, root1, b1, 0, 1);      // g_h1 = x @ root1 + b1
    agg_kernel<<<(NN * 32 + 255) / 256, 256>>>(1);             // g_h1 = relu(g_h1 + agg)

    // layer 2
    gemm_kernel<64><<<gcat, 256>>>(nullptr, W2, nullptr, 1, 0);   // g_H = h1 @ W2[r]
    gemm_kernel<64><<<groot, 256>>>(nullptr, root2, b2, 1, 2);    // g_h2 = h1 @ root2 + b2
    agg_kernel<<<(NN * 32 + 255) / 256, 256>>>(2);                // g_h2 = relu(g_h2 + agg)

    // classifier + log_softmax
    final_kernel<<<(NN + 7) / 8, 256>>>(Wl, bl, out);
}

// round 3
// speedup vs baseline: 1.3269x; 1.3269x over previous
#include <cuda_runtime.h>
#include <cuda_bf16.h>
#include <math.h>

#define NN 50000
#define EE 800000
#define RR 8
#define SCAN_BLOCKS ((NN + 255) / 256)   // 196

typedef unsigned long long ull;

// ---------------- scratch ----------------------------------------------------
__device__ float    g_H[(size_t)NN * 512];    // [N, 8*64] per-relation projections
__device__ float    g_h1[(size_t)NN * 64];
__device__ float    g_h2[(size_t)NN * 64];
__device__ int      g_deg[NN];
__device__ int      g_cntdr[NN * RR];         // per (dst, rel) edge count
__device__ float    g_inv[NN * RR];           // 1 / max(cnt, 1)
__device__ int      g_indptr[NN + 1];
__device__ int      g_cursor[NN];
__device__ int      g_bsum[SCAN_BLOCKS];
__device__ unsigned g_packed[EE];             // (rel<<16)|src, grouped by dst
__device__ int      g_is64_idx;
__device__ int      g_is64_typ;

// ---------------- f32x2 helpers ----------------------------------------------
__device__ __forceinline__ ull f2pack(float x, float y) {
    ull r; asm("mov.b64 %0, {%1,%2};" : "=l"(r) : "f"(x), "f"(y)); return r;
}
__device__ __forceinline__ void ffma2(ull& d, ull a, ull b) {
    asm("fma.rn.f32x2 %0, %1, %2, %0;" : "+l"(d) : "l"(a), "l"(b));
}
__device__ __forceinline__ float2 f2unpack(ull v) {
    float2 r; asm("mov.b64 {%0,%1}, %2;" : "=f"(r.x), "=f"(r.y) : "l"(v)); return r;
}

// ---------------- dtype detection ---------------------------------------------
__global__ void detect_kernel(const unsigned* __restrict__ idx,
                              const unsigned* __restrict__ typ) {
    unsigned a = 0, b = 0;
    #pragma unroll
    for (int i = 0; i < 64; i++) { a |= idx[2 * i + 1]; b |= typ[2 * i + 1]; }
    g_is64_idx = (a == 0);
    g_is64_typ = (b == 0);
}
__device__ __forceinline__ int load_src(const void* ei, int e) {
    return g_is64_idx ? (int)((const long long*)ei)[e] : ((const int*)ei)[e];
}
__device__ __forceinline__ int load_dst(const void* ei, int e) {
    return g_is64_idx ? (int)((const long long*)ei)[EE + e] : ((const int*)ei)[EE + e];
}
__device__ __forceinline__ int load_rel(const void* et, int e) {
    return g_is64_typ ? (int)((const long long*)et)[e] : ((const int*)et)[e];
}

// ---------------- CSR build ----------------------------------------------------
__global__ void zero_kernel() {
    int i = blockIdx.x * blockDim.x + threadIdx.x;
    if (i < NN) g_deg[i] = 0;
    if (i < NN * RR) g_cntdr[i] = 0;
}

__global__ void hist_kernel(const void* __restrict__ ei, const void* __restrict__ et) {
    int e = blockIdx.x * blockDim.x + threadIdx.x;
    if (e >= EE) return;
    int dst = load_dst(ei, e);
    int rel = load_rel(et, e);
    if ((unsigned)dst < NN && (unsigned)rel < RR) {
        atomicAdd(&g_deg[dst], 1);
        atomicAdd(&g_cntdr[dst * RR + rel], 1);
    }
}

__global__ void inv_kernel() {
    int i = blockIdx.x * blockDim.x + threadIdx.x;
    if (i < NN * RR) g_inv[i] = 1.f / (float)max(g_cntdr[i], 1);
}

__device__ __forceinline__ int block_incl_scan256(int v, int t) {
    __shared__ int ws[8];
    int lane = t & 31, wid = t >> 5;
    int x = v;
    #pragma unroll
    for (int o = 1; o < 32; o <<= 1) {
        int y = __shfl_up_sync(0xffffffffu, x, o);
        if (lane >= o) x += y;
    }
    if (lane == 31) ws[wid] = x;
    __syncthreads();
    if (wid == 0) {
        int s = (lane < 8) ? ws[lane] : 0;
        #pragma unroll
        for (int o = 1; o < 8; o <<= 1) {
            int y = __shfl_up_sync(0xffffffffu, s, o);
            if (lane >= o) s += y;
        }
        if (lane < 8) ws[lane] = s;
    }
    __syncthreads();
    if (wid > 0) x += ws[wid - 1];
    return x;
}

__global__ void blocksum_kernel() {
    int b = blockIdx.x, t = threadIdx.x, i = b * 256 + t;
    int v = (i < NN) ? g_deg[i] : 0;
    __shared__ int sh[8];
    int lane = t & 31, wid = t >> 5;
    #pragma unroll
    for (int o = 16; o > 0; o >>= 1) v += __shfl_xor_sync(0xffffffffu, v, o);
    if (lane == 0) sh[wid] = v;
    __syncthreads();
    if (t == 0) {
        int s = 0;
        #pragma unroll
        for (int j = 0; j < 8; j++) s += sh[j];
        g_bsum[b] = s;
    }
}

__global__ void scanb_kernel() {
    int t = threadIdx.x;
    int v = (t < SCAN_BLOCKS) ? g_bsum[t] : 0;
    int incl = block_incl_scan256(v, t);
    __syncthreads();
    if (t < SCAN_BLOCKS) g_bsum[t] = incl - v;   // exclusive prefix
    if (t == SCAN_BLOCKS - 1) g_indptr[NN] = incl;
}

__global__ void offsets_kernel() {
    int b = blockIdx.x, t = threadIdx.x, i = b * 256 + t;
    int v = (i < NN) ? g_deg[i] : 0;
    int incl = block_incl_scan256(v, t);
    int excl = g_bsum[b] + incl - v;
    if (i < NN) { g_indptr[i] = excl; g_cursor[i] = excl; }
}

__global__ void scatter_kernel(const void* __restrict__ ei, const void* __restrict__ et) {
    int e = blockIdx.x * blockDim.x + threadIdx.x;
    if (e >= EE) return;
    int src = load_src(ei, e);
    int dst = load_dst(ei, e);
    int rel = load_rel(et, e);
    if ((unsigned)src >= NN || (unsigned)dst >= NN || (unsigned)rel >= RR) return;
    int pos = atomicAdd(&g_cursor[dst], 1);
    if ((unsigned)pos < EE) g_packed[pos] = ((unsigned)rel << 16) | (unsigned)src;
}

// ---------------- GEMM (FFMA2): grid.y == 9, y<8 -> g_H slice, y==8 -> root ----
template <int K>
__global__ void __launch_bounds__(256)
gemm_kernel(const float* __restrict__ Ain, const float* __restrict__ W,
            const float* __restrict__ root, const float* __restrict__ bias,
            int aSel, int layer) {
    __shared__ float As[16][132];
    __shared__ float Bs[16][64];

    const float* A = aSel ? g_h1 : Ain;
    int tid = threadIdx.x;
    int m0  = blockIdx.x * 128;
    int rel = blockIdx.y;

    const float* Wr; const float* bi = nullptr;
    float* C; int ldc, c0;
    if (rel < 8) { Wr = W + (size_t)rel * K * 64; C = g_H; ldc = 512; c0 = rel * 64; }
    else         { Wr = root; bi = bias; C = (layer == 1) ? g_h1 : g_h2; ldc = 64; c0 = 0; }

    ull acc[4][4];
    #pragma unroll
    for (int i = 0; i < 4; i++)
        #pragma unroll
        for (int j = 0; j < 4; j++) acc[i][j] = 0ull;

    int ar = tid >> 2;            // 0..63
    int ak = (tid & 3) * 4;
    int ty = tid >> 4, tx = tid & 15;

    for (int kt = 0; kt < K; kt += 16) {
        #pragma unroll
        for (int s = 0; s < 2; s++) {
            int row = m0 + ar + s * 64;
            float4 v = make_float4(0.f, 0.f, 0.f, 0.f);
            if (row < NN) v = *(const float4*)&A[(size_t)row * K + kt + ak];
            As[ak + 0][ar + s * 64] = v.x;
            As[ak + 1][ar + s * 64] = v.y;
            As[ak + 2][ar + s * 64] = v.z;
            As[ak + 3][ar + s * 64] = v.w;
        }
        {
            float4 v = *(const float4*)&Wr[(size_t)(kt + ty) * 64 + tx * 4];
            *(float4*)&Bs[ty][tx * 4] = v;
        }
        __syncthreads();
        #pragma unroll
        for (int k = 0; k < 16; k++) {
            ull a2[4];
            #pragma unroll
            for (int i = 0; i < 4; i++)
                a2[i] = *(const ull*)&As[k][ty * 8 + 2 * i];   // rows (2i, 2i+1)
            float4 b = *(const float4*)&Bs[k][tx * 4];
            ull b2[4] = { f2pack(b.x, b.x), f2pack(b.y, b.y),
                          f2pack(b.z, b.z), f2pack(b.w, b.w) };
            #pragma unroll
            for (int i = 0; i < 4; i++)
                #pragma unroll
                for (int j = 0; j < 4; j++) ffma2(acc[i][j], a2[i], b2[j]);
        }
        __syncthreads();
    }

    #pragma unroll
    for (int i = 0; i < 4; i++) {
        float2 c0v = f2unpack(acc[i][0]);
        float2 c1v = f2unpack(acc[i][1]);
        float2 c2v = f2unpack(acc[i][2]);
        float2 c3v = f2unpack(acc[i][3]);
        float4 lo = make_float4(c0v.x, c1v.x, c2v.x, c3v.x);  // row 2i
        float4 hi = make_float4(c0v.y, c1v.y, c2v.y, c3v.y);  // row 2i+1
        if (bi) {
            float4 bb = *(const float4*)&bi[tx * 4];
            lo.x += bb.x; lo.y += bb.y; lo.z += bb.z; lo.w += bb.w;
            hi.x += bb.x; hi.y += bb.y; hi.z += bb.z; hi.w += bb.w;
        }
        int r0 = m0 + ty * 8 + 2 * i;
        if (r0 < NN)     *(float4*)&C[(size_t)r0 * ldc + c0 + tx * 4] = lo;
        if (r0 + 1 < NN) *(float4*)&C[(size_t)(r0 + 1) * ldc + c0 + tx * 4] = hi;
    }
}

// ---------------- aggregation: one warp per dst node ---------------------------
__global__ void agg_kernel(int sel) {
    int gw   = (blockIdx.x * blockDim.x + threadIdx.x) >> 5;
    int lane = threadIdx.x & 31;
    if (gw >= NN) return;
    float* h = (sel == 1) ? g_h1 : g_h2;
    int beg = g_indptr[gw], end = g_indptr[gw + 1];

    float inv8 = (lane < 8) ? g_inv[gw * RR + lane] : 0.f;

    float ax = 0.f, ay = 0.f;
    for (int e = beg; e < end; e++) {
        unsigned p = g_packed[e];
        int rel = p >> 16;
        int src = p & 0xffff;
        float inv = __shfl_sync(0xffffffffu, inv8, rel);
        float2 v = *(const float2*)&g_H[(size_t)src * 512 + rel * 64 + lane * 2];
        ax = fmaf(v.x, inv, ax);
        ay = fmaf(v.y, inv, ay);
    }

    float2 base = *(const float2*)&h[(size_t)gw * 64 + lane * 2];
    float o0 = base.x + ax, o1 = base.y + ay;
    o0 = o0 > 0.f ? o0 : 0.f;
    o1 = o1 > 0.f ? o1 : 0.f;
    *(float2*)&h[(size_t)gw * 64 + lane * 2] = make_float2(o0, o1);
}

// ---------------- final: logits = h2 @ Wl + bl, then log_softmax ----------------
__global__ void __launch_bounds__(256)
final_kernel(const float* __restrict__ Wl, const float* __restrict__ bl,
             float* __restrict__ out) {
    __shared__ float sW[64 * 40];
    __shared__ float sb[40];
    __shared__ float srow[8][64];
    int t = threadIdx.x;
    for (int i = t; i < 64 * 40; i += 256) sW[i] = Wl[i];
    if (t < 40) sb[t] = bl[t];
    __syncthreads();

    int warp = t >> 5, lane = t & 31;
    int n = blockIdx.x * 8 + warp;
    if (n < NN) {
        srow[warp][lane]      = g_h2[(size_t)n * 64 + lane];
        srow[warp][lane + 32] = g_h2[(size_t)n * 64 + 32 + lane];
    }
    __syncwarp();

    float v1 = -1e30f, v2 = -1e30f;
    if (n < NN) {
        float d = sb[lane];
        #pragma unroll
        for (int k = 0; k < 64; k++) d += srow[warp][k] * sW[k * 40 + lane];
        v1 = d;
        if (lane < 8) {
            float d2 = sb[lane + 32];
            #pragma unroll
            for (int k = 0; k < 64; k++) d2 += srow[warp][k] * sW[k * 40 + lane + 32];
            v2 = d2;
        }
    }
    float m = fmaxf(v1, v2);
    #pragma unroll
    for (int o = 16; o > 0; o >>= 1) m = fmaxf(m, __shfl_xor_sync(0xffffffffu, m, o));
    float e1 = __expf(v1 - m);
    float e2 = (lane < 8) ? __expf(v2 - m) : 0.f;
    float s = e1 + e2;
    #pragma unroll
    for (int o = 16; o > 0; o >>= 1) s += __shfl_xor_sync(0xffffffffu, s, o);
    float lse = m + __logf(s);
    if (n < NN) {
        out[(size_t)n * 40 + lane] = v1 - lse;
        if (lane < 8) out[(size_t)n * 40 + 32 + lane] = v2 - lse;
    }
}

// ---------------- launch ---------------------------------------------------------
extern "C" void kernel_launch(void* const* d_in, const int* in_sizes, int n_in,
                              void* d_out, int out_size) {
    const float* x     = (const float*)d_in[0];
    const void*  ei    = d_in[1];
    const void*  et    = d_in[2];
    const float* W1    = (const float*)d_in[3];
    const float* root1 = (const float*)d_in[4];
    const float* b1    = (const float*)d_in[5];
    const float* W2    = (const float*)d_in[6];
    const float* root2 = (const float*)d_in[7];
    const float* b2    = (const float*)d_in[8];
    const float* Wl    = (const float*)d_in[9];
    const float* bl    = (const float*)d_in[10];
    float*       out   = (float*)d_out;

    detect_kernel<<<1, 1>>>((const unsigned*)ei, (const unsigned*)et);
    zero_kernel<<<(NN * RR + 255) / 256, 256>>>();
    hist_kernel<<<(EE + 255) / 256, 256>>>(ei, et);
    inv_kernel<<<(NN * RR + 255) / 256, 256>>>();
    blocksum_kernel<<<SCAN_BLOCKS, 256>>>();
    scanb_kernel<<<1, 256>>>();
    offsets_kernel<<<SCAN_BLOCKS, 256>>>();
    scatter_kernel<<<(EE + 255) / 256, 256>>>(ei, et);

    dim3 g9((NN + 127) / 128, 9);

    // layer 1: g_H = x@W1[r] (r<8), g_h1 = x@root1 + b1 (r==8)
    gemm_kernel<128><<<g9, 256>>>(x, W1, root1, b1, 0, 1);
    agg_kernel<<<(NN * 32 + 255) / 256, 256>>>(1);

    // layer 2
    gemm_kernel<64><<<g9, 256>>>(nullptr, W2, root2, b2, 1, 2);
    agg_kernel<<<(NN * 32 + 255) / 256, 256>>>(2);

    final_kernel<<<(NN + 7) / 8, 256>>>(Wl, bl, out);
}

// round 4
// speedup vs baseline: 1.6276x; 1.2266x over previous
#include <cuda_runtime.h>
#include <cuda_bf16.h>
#include <math.h>

#define NN 50000
#define EE 800000
#define RR 8
#define SCAN_BLOCKS ((NN + 255) / 256)   // 196

typedef unsigned long long ull;
typedef __nv_bfloat16 bf16;

// ---------------- scratch ----------------------------------------------------
__device__ float    g_H[(size_t)NN * 512];
__device__ float    g_h1[(size_t)NN * 64];
__device__ float    g_h2[(size_t)NN * 64];
__device__ bf16     g_xhi[(size_t)NN * 128];
__device__ bf16     g_xlo[(size_t)NN * 128];
__device__ bf16     g_ahi[(size_t)NN * 64];
__device__ bf16     g_alo[(size_t)NN * 64];
__device__ bf16     g_whi[9 * 128 * 64];
__device__ bf16     g_wlo[9 * 128 * 64];
__device__ int      g_deg[NN];
__device__ int      g_cntdr[NN * RR];
__device__ float    g_inv[NN * RR];
__device__ int      g_indptr[NN + 1];
__device__ int      g_cursor[NN];
__device__ int      g_bsum[SCAN_BLOCKS];
__device__ unsigned g_packed[EE];
__device__ int      g_is64_idx;
__device__ int      g_is64_typ;

// ---------------- dtype detection ---------------------------------------------
__global__ void detect_kernel(const unsigned* __restrict__ idx,
                              const unsigned* __restrict__ typ) {
    unsigned a = 0, b = 0;
    #pragma unroll
    for (int i = 0; i < 64; i++) { a |= idx[2 * i + 1]; b |= typ[2 * i + 1]; }
    g_is64_idx = (a == 0);
    g_is64_typ = (b == 0);
}
__device__ __forceinline__ int load_src(const void* ei, int e) {
    return g_is64_idx ? (int)((const long long*)ei)[e] : ((const int*)ei)[e];
}
__device__ __forceinline__ int load_dst(const void* ei, int e) {
    return g_is64_idx ? (int)((const long long*)ei)[EE + e] : ((const int*)ei)[EE + e];
}
__device__ __forceinline__ int load_rel(const void* et, int e) {
    return g_is64_typ ? (int)((const long long*)et)[e] : ((const int*)et)[e];
}

// ---------------- CSR build ----------------------------------------------------
__global__ void zero_kernel() {
    int i = blockIdx.x * blockDim.x + threadIdx.x;
    if (i < NN) g_deg[i] = 0;
    if (i < NN * RR) g_cntdr[i] = 0;
}

__global__ void hist_kernel(const void* __restrict__ ei, const void* __restrict__ et) {
    int e = blockIdx.x * blockDim.x + threadIdx.x;
    if (e >= EE) return;
    int dst = load_dst(ei, e);
    int rel = load_rel(et, e);
    if ((unsigned)dst < NN && (unsigned)rel < RR) {
        atomicAdd(&g_deg[dst], 1);
        atomicAdd(&g_cntdr[dst * RR + rel], 1);
    }
}

__global__ void inv_kernel() {
    int i = blockIdx.x * blockDim.x + threadIdx.x;
    if (i < NN * RR) g_inv[i] = 1.f / (float)max(g_cntdr[i], 1);
}

__device__ __forceinline__ int block_incl_scan256(int v, int t) {
    __shared__ int ws[8];
    int lane = t & 31, wid = t >> 5;
    int x = v;
    #pragma unroll
    for (int o = 1; o < 32; o <<= 1) {
        int y = __shfl_up_sync(0xffffffffu, x, o);
        if (lane >= o) x += y;
    }
    if (lane == 31) ws[wid] = x;
    __syncthreads();
    if (wid == 0) {
        int s = (lane < 8) ? ws[lane] : 0;
        #pragma unroll
        for (int o = 1; o < 8; o <<= 1) {
            int y = __shfl_up_sync(0xffffffffu, s, o);
            if (lane >= o) s += y;
        }
        if (lane < 8) ws[lane] = s;
    }
    __syncthreads();
    if (wid > 0) x += ws[wid - 1];
    return x;
}

__global__ void blocksum_kernel() {
    int b = blockIdx.x, t = threadIdx.x, i = b * 256 + t;
    int v = (i < NN) ? g_deg[i] : 0;
    __shared__ int sh[8];
    int lane = t & 31, wid = t >> 5;
    #pragma unroll
    for (int o = 16; o > 0; o >>= 1) v += __shfl_xor_sync(0xffffffffu, v, o);
    if (lane == 0) sh[wid] = v;
    __syncthreads();
    if (t == 0) {
        int s = 0;
        #pragma unroll
        for (int j = 0; j < 8; j++) s += sh[j];
        g_bsum[b] = s;
    }
}

__global__ void scanb_kernel() {
    int t = threadIdx.x;
    int v = (t < SCAN_BLOCKS) ? g_bsum[t] : 0;
    int incl = block_incl_scan256(v, t);
    __syncthreads();
    if (t < SCAN_BLOCKS) g_bsum[t] = incl - v;
    if (t == SCAN_BLOCKS - 1) g_indptr[NN] = incl;
}

__global__ void offsets_kernel() {
    int b = blockIdx.x, t = threadIdx.x, i = b * 256 + t;
    int v = (i < NN) ? g_deg[i] : 0;
    int incl = block_incl_scan256(v, t);
    int excl = g_bsum[b] + incl - v;
    if (i < NN) { g_indptr[i] = excl; g_cursor[i] = excl; }
}

__global__ void scatter_kernel(const void* __restrict__ ei, const void* __restrict__ et) {
    int e = blockIdx.x * blockDim.x + threadIdx.x;
    if (e >= EE) return;
    int src = load_src(ei, e);
    int dst = load_dst(ei, e);
    int rel = load_rel(et, e);
    if ((unsigned)src >= NN || (unsigned)dst >= NN || (unsigned)rel >= RR) return;
    int pos = atomicAdd(&g_cursor[dst], 1);
    if ((unsigned)pos < EE) g_packed[pos] = ((unsigned)rel << 16) | (unsigned)src;
}

// ---------------- fp32 -> split bf16 (hi + lo) ---------------------------------
__global__ void cvt_kernel(const float* __restrict__ in, bf16* __restrict__ hi,
                           bf16* __restrict__ lo, int n2) {
    int i = blockIdx.x * blockDim.x + threadIdx.x;
    if (i >= n2) return;
    float2 v = ((const float2*)in)[i];
    bf16 hx = __float2bfloat16(v.x);
    bf16 hy = __float2bfloat16(v.y);
    bf16 lx = __float2bfloat16(v.x - __bfloat162float(hx));
    bf16 ly = __float2bfloat16(v.y - __bfloat162float(hy));
    ((__nv_bfloat162*)hi)[i] = __nv_bfloat162(hx, hy);
    ((__nv_bfloat162*)lo)[i] = __nv_bfloat162(lx, ly);
}

// ---------------- tensor-core helpers ------------------------------------------
__device__ __forceinline__ unsigned smem_u32(const void* p) {
    return (unsigned)__cvta_generic_to_shared(p);
}
__device__ __forceinline__ void ldsm4(unsigned& r0, unsigned& r1, unsigned& r2,
                                      unsigned& r3, unsigned addr) {
    asm volatile("ldmatrix.sync.aligned.m8n8.x4.shared.b16 {%0,%1,%2,%3}, [%4];"
                 : "=r"(r0), "=r"(r1), "=r"(r2), "=r"(r3) : "r"(addr));
}
__device__ __forceinline__ void ldsm4t(unsigned& r0, unsigned& r1, unsigned& r2,
                                       unsigned& r3, unsigned addr) {
    asm volatile("ldmatrix.sync.aligned.m8n8.x4.trans.shared.b16 {%0,%1,%2,%3}, [%4];"
                 : "=r"(r0), "=r"(r1), "=r"(r2), "=r"(r3) : "r"(addr));
}
__device__ __forceinline__ void mma16816(float* d, unsigned a0, unsigned a1,
                                         unsigned a2, unsigned a3,
                                         unsigned b0, unsigned b1) {
    asm volatile(
        "mma.sync.aligned.m16n8k16.row.col.f32.bf16.bf16.f32 "
        "{%0,%1,%2,%3},{%4,%5,%6,%7},{%8,%9},{%0,%1,%2,%3};"
        : "+f"(d[0]), "+f"(d[1]), "+f"(d[2]), "+f"(d[3])
        : "r"(a0), "r"(a1), "r"(a2), "r"(a3), "r"(b0), "r"(b1));
}

// ---------------- tensor GEMM: C[128 x 64] per block, split-bf16 3-mma ----------
// grid.y == 9: y<8 -> g_H slice (ldc 512), y==8 -> root into g_h1/g_h2 (+bias)
template <int K>
__global__ void __launch_bounds__(256)
tgemm_kernel(const bf16* __restrict__ Ahi, const bf16* __restrict__ Alo,
             const float* __restrict__ bias, int layer) {
    __shared__ bf16 sAhi[128 * 40], sAlo[128 * 40];   // row stride 40 (80 B)
    __shared__ bf16 sBhi[32 * 72],  sBlo[32 * 72];    // row stride 72 (144 B)

    int tid = threadIdx.x, warp = tid >> 5, lane = tid & 31;
    int m0 = blockIdx.x * 128, rel = blockIdx.y;

    const bf16* Whi = g_whi + (size_t)rel * K * 64;
    const bf16* Wlo = g_wlo + (size_t)rel * K * 64;

    float* C; int ldc, c0;
    if (rel < 8) { C = g_H; ldc = 512; c0 = rel * 64; }
    else         { C = (layer == 1) ? g_h1 : g_h2; ldc = 64; c0 = 0; }

    float acc[8][4];
    #pragma unroll
    for (int j = 0; j < 8; j++)
        #pragma unroll
        for (int i = 0; i < 4; i++) acc[j][i] = 0.f;

    const uint4 z4 = make_uint4(0, 0, 0, 0);

    for (int kt = 0; kt < K; kt += 32) {
        __syncthreads();
        // A chunk: 128 rows x 32 bf16 (hi & lo)
        #pragma unroll
        for (int i = 0; i < 2; i++) {
            int seg = tid + i * 256;          // 0..511
            int row = seg >> 2, s = seg & 3;
            int gr = m0 + row;
            uint4 vh = z4, vl = z4;
            if (gr < NN) {
                vh = *(const uint4*)&Ahi[(size_t)gr * K + kt + s * 8];
                vl = *(const uint4*)&Alo[(size_t)gr * K + kt + s * 8];
            }
            *(uint4*)&sAhi[row * 40 + s * 8] = vh;
            *(uint4*)&sAlo[row * 40 + s * 8] = vl;
        }
        // B chunk: 32 rows x 64 bf16 (hi & lo)
        {
            int row = tid >> 3, s = tid & 7;
            *(uint4*)&sBhi[row * 72 + s * 8] = *(const uint4*)&Whi[(size_t)(kt + row) * 64 + s * 8];
            *(uint4*)&sBlo[row * 72 + s * 8] = *(const uint4*)&Wlo[(size_t)(kt + row) * 64 + s * 8];
        }
        __syncthreads();

        #pragma unroll
        for (int ks = 0; ks < 32; ks += 16) {
            unsigned ah[4], al[4];
            unsigned aoff = (warp * 16 + (lane & 15)) * 40 + ks + (lane >> 4) * 8;
            ldsm4(ah[0], ah[1], ah[2], ah[3], smem_u32(&sAhi[aoff]));
            ldsm4(al[0], al[1], al[2], al[3], smem_u32(&sAlo[aoff]));
            #pragma unroll
            for (int jj = 0; jj < 4; jj++) {
                int g = lane >> 3;
                int brow = ks + (lane & 7) + (g & 1) * 8;
                int bcol = jj * 16 + (g >> 1) * 8;
                unsigned bh[4], bl[4];
                ldsm4t(bh[0], bh[1], bh[2], bh[3], smem_u32(&sBhi[brow * 72 + bcol]));
                ldsm4t(bl[0], bl[1], bl[2], bl[3], smem_u32(&sBlo[brow * 72 + bcol]));
                // n-tile 2jj
                mma16816(acc[2 * jj], ah[0], ah[1], ah[2], ah[3], bh[0], bh[1]);
                mma16816(acc[2 * jj], ah[0], ah[1], ah[2], ah[3], bl[0], bl[1]);
                mma16816(acc[2 * jj], al[0], al[1], al[2], al[3], bh[0], bh[1]);
                // n-tile 2jj+1
                mma16816(acc[2 * jj + 1], ah[0], ah[1], ah[2], ah[3], bh[2], bh[3]);
                mma16816(acc[2 * jj + 1], ah[0], ah[1], ah[2], ah[3], bl[2], bl[3]);
                mma16816(acc[2 * jj + 1], al[0], al[1], al[2], al[3], bh[2], bh[3]);
            }
        }
    }

    // epilogue
    int row = m0 + warp * 16 + (lane >> 2);
    int cb  = (lane & 3) * 2;
    #pragma unroll
    for (int j = 0; j < 8; j++) {
        int col = j * 8 + cb;
        float b0 = 0.f, b1 = 0.f;
        if (rel == 8) { b0 = bias[col]; b1 = bias[col + 1]; }
        if (row < NN)
            *(float2*)&C[(size_t)row * ldc + c0 + col] =
                make_float2(acc[j][0] + b0, acc[j][1] + b1);
        if (row + 8 < NN)
            *(float2*)&C[(size_t)(row + 8) * ldc + c0 + col] =
                make_float2(acc[j][2] + b0, acc[j][3] + b1);
    }
}

// ---------------- aggregation: one warp per dst node ---------------------------
__global__ void agg_kernel(int sel) {
    int gw   = (blockIdx.x * blockDim.x + threadIdx.x) >> 5;
    int lane = threadIdx.x & 31;
    if (gw >= NN) return;
    float* h = (sel == 1) ? g_h1 : g_h2;
    int beg = g_indptr[gw], end = g_indptr[gw + 1];

    float inv8 = (lane < 8) ? g_inv[gw * RR + lane] : 0.f;

    float ax = 0.f, ay = 0.f;
    for (int e = beg; e < end; e++) {
        unsigned p = g_packed[e];
        int rel = p >> 16;
        int src = p & 0xffff;
        float inv = __shfl_sync(0xffffffffu, inv8, rel);
        float2 v = *(const float2*)&g_H[(size_t)src * 512 + rel * 64 + lane * 2];
        ax = fmaf(v.x, inv, ax);
        ay = fmaf(v.y, inv, ay);
    }

    float2 base = *(const float2*)&h[(size_t)gw * 64 + lane * 2];
    float o0 = base.x + ax, o1 = base.y + ay;
    o0 = o0 > 0.f ? o0 : 0.f;
    o1 = o1 > 0.f ? o1 : 0.f;
    *(float2*)&h[(size_t)gw * 64 + lane * 2] = make_float2(o0, o1);
}

// ---------------- final: logits = h2 @ Wl + bl, then log_softmax ----------------
__global__ void __launch_bounds__(256)
final_kernel(const float* __restrict__ Wl, const float* __restrict__ bl,
             float* __restrict__ out) {
    __shared__ float sW[64 * 40];
    __shared__ float sb[40];
    __shared__ float srow[8][64];
    int t = threadIdx.x;
    for (int i = t; i < 64 * 40; i += 256) sW[i] = Wl[i];
    if (t < 40) sb[t] = bl[t];
    __syncthreads();

    int warp = t >> 5, lane = t & 31;
    int n = blockIdx.x * 8 + warp;
    if (n < NN) {
        srow[warp][lane]      = g_h2[(size_t)n * 64 + lane];
        srow[warp][lane + 32] = g_h2[(size_t)n * 64 + 32 + lane];
    }
    __syncwarp();

    float v1 = -1e30f, v2 = -1e30f;
    if (n < NN) {
        float d = sb[lane];
        #pragma unroll
        for (int k = 0; k < 64; k++) d += srow[warp][k] * sW[k * 40 + lane];
        v1 = d;
        if (lane < 8) {
            float d2 = sb[lane + 32];
            #pragma unroll
            for (int k = 0; k < 64; k++) d2 += srow[warp][k] * sW[k * 40 + lane + 32];
            v2 = d2;
        }
    }
    float m = fmaxf(v1, v2);
    #pragma unroll
    for (int o = 16; o > 0; o >>= 1) m = fmaxf(m, __shfl_xor_sync(0xffffffffu, m, o));
    float e1 = __expf(v1 - m);
    float e2 = (lane < 8) ? __expf(v2 - m) : 0.f;
    float s = e1 + e2;
    #pragma unroll
    for (int o = 16; o > 0; o >>= 1) s += __shfl_xor_sync(0xffffffffu, s, o);
    float lse = m + __logf(s);
    if (n < NN) {
        out[(size_t)n * 40 + lane] = v1 - lse;
        if (lane < 8) out[(size_t)n * 40 + 32 + lane] = v2 - lse;
    }
}

// ---------------- launch ---------------------------------------------------------
extern "C" void kernel_launch(void* const* d_in, const int* in_sizes, int n_in,
                              void* d_out, int out_size) {
    const float* x     = (const float*)d_in[0];
    const void*  ei    = d_in[1];
    const void*  et    = d_in[2];
    const float* W1    = (const float*)d_in[3];
    const float* root1 = (const float*)d_in[4];
    const float* b1    = (const float*)d_in[5];
    const float* W2    = (const float*)d_in[6];
    const float* root2 = (const float*)d_in[7];
    const float* b2    = (const float*)d_in[8];
    const float* Wl    = (const float*)d_in[9];
    const float* bl    = (const float*)d_in[10];
    float*       out   = (float*)d_out;

    bf16 *whi, *wlo, *xhi, *xlo, *ahi, *alo;
    cudaGetSymbolAddress((void**)&whi, g_whi);
    cudaGetSymbolAddress((void**)&wlo, g_wlo);
    cudaGetSymbolAddress((void**)&xhi, g_xhi);
    cudaGetSymbolAddress((void**)&xlo, g_xlo);
    cudaGetSymbolAddress((void**)&ahi, g_ahi);
    cudaGetSymbolAddress((void**)&alo, g_alo);
    float *h1p;
    cudaGetSymbolAddress((void**)&h1p, g_h1);

    // CSR build
    detect_kernel<<<1, 1>>>((const unsigned*)ei, (const unsigned*)et);
    zero_kernel<<<(NN * RR + 255) / 256, 256>>>();
    hist_kernel<<<(EE + 255) / 256, 256>>>(ei, et);
    inv_kernel<<<(NN * RR + 255) / 256, 256>>>();
    blocksum_kernel<<<SCAN_BLOCKS, 256>>>();
    scanb_kernel<<<1, 256>>>();
    offsets_kernel<<<SCAN_BLOCKS, 256>>>();
    scatter_kernel<<<(EE + 255) / 256, 256>>>(ei, et);

    dim3 g9((NN + 127) / 128, 9);

    // layer 1: split-convert inputs & weights, tensor GEMM, aggregate
    cvt_kernel<<<(NN * 128 / 2 + 255) / 256, 256>>>(x, xhi, xlo, NN * 128 / 2);
    cvt_kernel<<<(8 * 128 * 64 / 2 + 255) / 256, 256>>>(W1, whi, wlo, 8 * 128 * 64 / 2);
    cvt_kernel<<<(128 * 64 / 2 + 255) / 256, 256>>>(root1, whi + 8 * 128 * 64,
                                                    wlo + 8 * 128 * 64, 128 * 64 / 2);
    tgemm_kernel<128><<<g9, 256>>>(xhi, xlo, b1, 1);
    agg_kernel<<<(NN * 32 + 255) / 256, 256>>>(1);

    // layer 2
    cvt_kernel<<<(NN * 64 / 2 + 255) / 256, 256>>>(h1p, ahi, alo, NN * 64 / 2);
    cvt_kernel<<<(8 * 64 * 64 / 2 + 255) / 256, 256>>>(W2, whi, wlo, 8 * 64 * 64 / 2);
    cvt_kernel<<<(64 * 64 / 2 + 255) / 256, 256>>>(root2, whi + 8 * 64 * 64,
                                                   wlo + 8 * 64 * 64, 64 * 64 / 2);
    tgemm_kernel<64><<<g9, 256>>>(ahi, alo, b2, 2);
    agg_kernel<<<(NN * 32 + 255) / 256, 256>>>(2);

    final_kernel<<<(NN + 7) / 8, 256>>>(Wl, bl, out);
}

// round 5
// speedup vs baseline: 1.9464x; 1.1959x over previous
#include <cuda_runtime.h>
#include <cuda_bf16.h>
#include <math.h>

#define NN 50000
#define EE 800000
#define RR 8
#define SCAN_BLOCKS ((NN + 255) / 256)   // 196
#define W2OFF (9 * 128 * 64)             // layer-2 weight plane offset

typedef __nv_bfloat16 bf16;

// ---------------- scratch ----------------------------------------------------
__device__ float    g_H[(size_t)NN * 512];
__device__ float    g_h1[(size_t)NN * 64];
__device__ float    g_h2[(size_t)NN * 64];
__device__ bf16     g_xhi[(size_t)NN * 128];
__device__ bf16     g_ahi[(size_t)NN * 64];
__device__ bf16     g_whi[9 * 128 * 64 + 9 * 64 * 64];
__device__ bf16     g_wlo[9 * 128 * 64 + 9 * 64 * 64];
__device__ int      g_deg[NN];
__device__ int      g_cntdr[NN * RR];
__device__ float    g_inv[NN * RR];
__device__ int      g_indptr[NN + 1];
__device__ int      g_cursor[NN];
__device__ int      g_bsum[SCAN_BLOCKS];
__device__ unsigned g_packed[EE];
__device__ int      g_is64_idx;
__device__ int      g_is64_typ;

// ---------------- dtype helpers ------------------------------------------------
__device__ __forceinline__ int load_src(const void* ei, int e) {
    return g_is64_idx ? (int)((const long long*)ei)[e] : ((const int*)ei)[e];
}
__device__ __forceinline__ int load_dst(const void* ei, int e) {
    return g_is64_idx ? (int)((const long long*)ei)[EE + e] : ((const int*)ei)[EE + e];
}
__device__ __forceinline__ int load_rel(const void* et, int e) {
    return g_is64_typ ? (int)((const long long*)et)[e] : ((const int*)et)[e];
}

// ---------------- zero + dtype detect (fused) -----------------------------------
__global__ void zero_detect_kernel(const unsigned* __restrict__ idx,
                                   const unsigned* __restrict__ typ) {
    int i = blockIdx.x * blockDim.x + threadIdx.x;
    if (i < NN) g_deg[i] = 0;
    if (i < NN * RR) g_cntdr[i] = 0;
    if (i == 0) {
        unsigned a = 0, b = 0;
        #pragma unroll
        for (int k = 0; k < 64; k++) { a |= idx[2 * k + 1]; b |= typ[2 * k + 1]; }
        g_is64_idx = (a == 0);
        g_is64_typ = (b == 0);
    }
}

__global__ void hist_kernel(const void* __restrict__ ei, const void* __restrict__ et) {
    int e = blockIdx.x * blockDim.x + threadIdx.x;
    if (e >= EE) return;
    int dst = load_dst(ei, e);
    int rel = load_rel(et, e);
    if ((unsigned)dst < NN && (unsigned)rel < RR) {
        atomicAdd(&g_deg[dst], 1);
        atomicAdd(&g_cntdr[dst * RR + rel], 1);
    }
}

// ---------------- blocksum + inv (fused) ----------------------------------------
__global__ void blocksum_inv_kernel() {
    int b = blockIdx.x, t = threadIdx.x;
    int gi = b * 256 + t;
    if (gi < NN * RR) g_inv[gi] = 1.f / (float)max(g_cntdr[gi], 1);
    if (b < SCAN_BLOCKS) {
        int i = b * 256 + t;
        int v = (i < NN) ? g_deg[i] : 0;
        __shared__ int sh[8];
        int lane = t & 31, wid = t >> 5;
        #pragma unroll
        for (int o = 16; o > 0; o >>= 1) v += __shfl_xor_sync(0xffffffffu, v, o);
        if (lane == 0) sh[wid] = v;
        __syncthreads();
        if (t == 0) {
            int s = 0;
            #pragma unroll
            for (int j = 0; j < 8; j++) s += sh[j];
            g_bsum[b] = s;
        }
    }
}

__device__ __forceinline__ int block_incl_scan256(int v, int t) {
    __shared__ int ws[8];
    int lane = t & 31, wid = t >> 5;
    int x = v;
    #pragma unroll
    for (int o = 1; o < 32; o <<= 1) {
        int y = __shfl_up_sync(0xffffffffu, x, o);
        if (lane >= o) x += y;
    }
    if (lane == 31) ws[wid] = x;
    __syncthreads();
    if (wid == 0) {
        int s = (lane < 8) ? ws[lane] : 0;
        #pragma unroll
        for (int o = 1; o < 8; o <<= 1) {
            int y = __shfl_up_sync(0xffffffffu, s, o);
            if (lane >= o) s += y;
        }
        if (lane < 8) ws[lane] = s;
    }
    __syncthreads();
    if (wid > 0) x += ws[wid - 1];
    return x;
}

__global__ void scanb_kernel() {
    int t = threadIdx.x;
    int v = (t < SCAN_BLOCKS) ? g_bsum[t] : 0;
    int incl = block_incl_scan256(v, t);
    __syncthreads();
    if (t < SCAN_BLOCKS) g_bsum[t] = incl - v;
    if (t == SCAN_BLOCKS - 1) g_indptr[NN] = incl;
}

__global__ void offsets_kernel() {
    int b = blockIdx.x, t = threadIdx.x, i = b * 256 + t;
    int v = (i < NN) ? g_deg[i] : 0;
    int incl = block_incl_scan256(v, t);
    int excl = g_bsum[b] + incl - v;
    if (i < NN) { g_indptr[i] = excl; g_cursor[i] = excl; }
}

__global__ void scatter_kernel(const void* __restrict__ ei, const void* __restrict__ et) {
    int e = blockIdx.x * blockDim.x + threadIdx.x;
    if (e >= EE) return;
    int src = load_src(ei, e);
    int dst = load_dst(ei, e);
    int rel = load_rel(et, e);
    if ((unsigned)src >= NN || (unsigned)dst >= NN || (unsigned)rel >= RR) return;
    int pos = atomicAdd(&g_cursor[dst], 1);
    if ((unsigned)pos < EE) g_packed[pos] = ((unsigned)rel << 16) | (unsigned)src;
}

// ---------------- conversions ----------------------------------------------------
// fused conversion of all 4 weight tensors -> [W1 | root1 | W2 | root2] hi+lo
#define W1_F2   32768   // 8*128*64/2
#define R1_F2   4096
#define W2_F2   16384
#define R2_F2   2048
#define WT_F2   (W1_F2 + R1_F2 + W2_F2 + R2_F2)   // 55296

__global__ void cvtw_kernel(const float* __restrict__ W1, const float* __restrict__ r1,
                            const float* __restrict__ W2, const float* __restrict__ r2) {
    int i = blockIdx.x * blockDim.x + threadIdx.x;
    if (i >= WT_F2) return;
    const float2* src;
    int off;
    if (i < W1_F2)                { src = (const float2*)W1; off = i; }
    else if (i < W1_F2 + R1_F2)   { src = (const float2*)r1; off = i - W1_F2; }
    else if (i < W1_F2 + R1_F2 + W2_F2) { src = (const float2*)W2; off = i - W1_F2 - R1_F2; }
    else                          { src = (const float2*)r2; off = i - W1_F2 - R1_F2 - W2_F2; }
    float2 v = src[off];
    bf16 hx = __float2bfloat16(v.x);
    bf16 hy = __float2bfloat16(v.y);
    bf16 lx = __float2bfloat16(v.x - __bfloat162float(hx));
    bf16 ly = __float2bfloat16(v.y - __bfloat162float(hy));
    ((__nv_bfloat162*)g_whi)[i] = __nv_bfloat162(hx, hy);
    ((__nv_bfloat162*)g_wlo)[i] = __nv_bfloat162(lx, ly);
}

__global__ void cvtx_kernel(const float* __restrict__ in, int n2) {
    int i = blockIdx.x * blockDim.x + threadIdx.x;
    if (i >= n2) return;
    float2 v = ((const float2*)in)[i];
    ((__nv_bfloat162*)g_xhi)[i] =
        __nv_bfloat162(__float2bfloat16(v.x), __float2bfloat16(v.y));
}

// ---------------- tensor-core helpers ------------------------------------------
__device__ __forceinline__ unsigned smem_u32(const void* p) {
    return (unsigned)__cvta_generic_to_shared(p);
}
__device__ __forceinline__ void ldsm4(unsigned& r0, unsigned& r1, unsigned& r2,
                                      unsigned& r3, unsigned addr) {
    asm volatile("ldmatrix.sync.aligned.m8n8.x4.shared.b16 {%0,%1,%2,%3}, [%4];"
                 : "=r"(r0), "=r"(r1), "=r"(r2), "=r"(r3) : "r"(addr));
}
__device__ __forceinline__ void ldsm4t(unsigned& r0, unsigned& r1, unsigned& r2,
                                       unsigned& r3, unsigned addr) {
    asm volatile("ldmatrix.sync.aligned.m8n8.x4.trans.shared.b16 {%0,%1,%2,%3}, [%4];"
                 : "=r"(r0), "=r"(r1), "=r"(r2), "=r"(r3) : "r"(addr));
}
__device__ __forceinline__ void mma16816(float* d, unsigned a0, unsigned a1,
                                         unsigned a2, unsigned a3,
                                         unsigned b0, unsigned b1) {
    asm volatile(
        "mma.sync.aligned.m16n8k16.row.col.f32.bf16.bf16.f32 "
        "{%0,%1,%2,%3},{%4,%5,%6,%7},{%8,%9},{%0,%1,%2,%3};"
        : "+f"(d[0]), "+f"(d[1]), "+f"(d[2]), "+f"(d[3])
        : "r"(a0), "r"(a1), "r"(a2), "r"(a3), "r"(b0), "r"(b1));
}

// ---------------- tensor GEMM: C[128 x 64] per block, 2-mma split-B -------------
template <int K>
__global__ void __launch_bounds__(256)
tgemm_kernel(const bf16* __restrict__ Ahi, const float* __restrict__ bias,
             int woff, int layer) {
    __shared__ bf16 sA[128 * 40];                     // row stride 40 (80 B)
    __shared__ bf16 sBhi[32 * 72], sBlo[32 * 72];     // row stride 72 (144 B)

    int tid = threadIdx.x, warp = tid >> 5, lane = tid & 31;
    int m0 = blockIdx.x * 128, rel = blockIdx.y;

    const bf16* Whi = g_whi + woff + (size_t)rel * K * 64;
    const bf16* Wlo = g_wlo + woff + (size_t)rel * K * 64;

    float* C; int ldc, c0;
    if (rel < 8) { C = g_H; ldc = 512; c0 = rel * 64; }
    else         { C = (layer == 1) ? g_h1 : g_h2; ldc = 64; c0 = 0; }

    float acc[8][4];
    #pragma unroll
    for (int j = 0; j < 8; j++)
        #pragma unroll
        for (int i = 0; i < 4; i++) acc[j][i] = 0.f;

    const uint4 z4 = make_uint4(0, 0, 0, 0);

    for (int kt = 0; kt < K; kt += 32) {
        __syncthreads();
        #pragma unroll
        for (int i = 0; i < 2; i++) {
            int seg = tid + i * 256;
            int row = seg >> 2, s = seg & 3;
            int gr = m0 + row;
            uint4 vh = z4;
            if (gr < NN) vh = *(const uint4*)&Ahi[(size_t)gr * K + kt + s * 8];
            *(uint4*)&sA[row * 40 + s * 8] = vh;
        }
        {
            int row = tid >> 3, s = tid & 7;
            *(uint4*)&sBhi[row * 72 + s * 8] = *(const uint4*)&Whi[(size_t)(kt + row) * 64 + s * 8];
            *(uint4*)&sBlo[row * 72 + s * 8] = *(const uint4*)&Wlo[(size_t)(kt + row) * 64 + s * 8];
        }
        __syncthreads();

        #pragma unroll
        for (int ks = 0; ks < 32; ks += 16) {
            unsigned ah[4];
            unsigned aoff = (warp * 16 + (lane & 15)) * 40 + ks + (lane >> 4) * 8;
            ldsm4(ah[0], ah[1], ah[2], ah[3], smem_u32(&sA[aoff]));
            #pragma unroll
            for (int jj = 0; jj < 4; jj++) {
                int g = lane >> 3;
                int brow = ks + (lane & 7) + (g & 1) * 8;
                int bcol = jj * 16 + (g >> 1) * 8;
                unsigned bh[4], bl[4];
                ldsm4t(bh[0], bh[1], bh[2], bh[3], smem_u32(&sBhi[brow * 72 + bcol]));
                ldsm4t(bl[0], bl[1], bl[2], bl[3], smem_u32(&sBlo[brow * 72 + bcol]));
                mma16816(acc[2 * jj],     ah[0], ah[1], ah[2], ah[3], bh[0], bh[1]);
                mma16816(acc[2 * jj],     ah[0], ah[1], ah[2], ah[3], bl[0], bl[1]);
                mma16816(acc[2 * jj + 1], ah[0], ah[1], ah[2], ah[3], bh[2], bh[3]);
                mma16816(acc[2 * jj + 1], ah[0], ah[1], ah[2], ah[3], bl[2], bl[3]);
            }
        }
    }

    int row = m0 + warp * 16 + (lane >> 2);
    int cb  = (lane & 3) * 2;
    #pragma unroll
    for (int j = 0; j < 8; j++) {
        int col = j * 8 + cb;
        float b0 = 0.f, b1 = 0.f;
        if (rel == 8) { b0 = bias[col]; b1 = bias[col + 1]; }
        if (row < NN)
            *(float2*)&C[(size_t)row * ldc + c0 + col] =
                make_float2(acc[j][0] + b0, acc[j][1] + b1);
        if (row + 8 < NN)
            *(float2*)&C[(size_t)(row + 8) * ldc + c0 + col] =
                make_float2(acc[j][2] + b0, acc[j][3] + b1);
    }
}

// ---------------- aggregation: warp per node, MLP-4 gather ----------------------
// sel==1: base g_h1, write relu(...) as bf16 -> g_ahi (layer-2 A input)
// sel==2: base g_h2, write relu(...) fp32 -> g_h2
__global__ void agg_kernel(int sel) {
    int gw   = (blockIdx.x * blockDim.x + threadIdx.x) >> 5;
    int lane = threadIdx.x & 31;
    if (gw >= NN) return;
    int beg = g_indptr[gw], end = g_indptr[gw + 1];

    float inv8 = (lane < 8) ? g_inv[gw * RR + lane] : 0.f;

    float ax = 0.f, ay = 0.f;
    int e = beg;
    for (; e + 4 <= end; e += 4) {
        unsigned p0 = g_packed[e],     p1 = g_packed[e + 1];
        unsigned p2 = g_packed[e + 2], p3 = g_packed[e + 3];
        const float2* a0 = (const float2*)&g_H[(size_t)(p0 & 0xffff) * 512 + (p0 >> 16) * 64 + lane * 2];
        const float2* a1 = (const float2*)&g_H[(size_t)(p1 & 0xffff) * 512 + (p1 >> 16) * 64 + lane * 2];
        const float2* a2 = (const float2*)&g_H[(size_t)(p2 & 0xffff) * 512 + (p2 >> 16) * 64 + lane * 2];
        const float2* a3 = (const float2*)&g_H[(size_t)(p3 & 0xffff) * 512 + (p3 >> 16) * 64 + lane * 2];
        float2 v0 = *a0, v1 = *a1, v2 = *a2, v3 = *a3;
        float i0 = __shfl_sync(0xffffffffu, inv8, p0 >> 16);
        float i1 = __shfl_sync(0xffffffffu, inv8, p1 >> 16);
        float i2 = __shfl_sync(0xffffffffu, inv8, p2 >> 16);
        float i3 = __shfl_sync(0xffffffffu, inv8, p3 >> 16);
        ax = fmaf(v0.x, i0, ax); ay = fmaf(v0.y, i0, ay);
        ax = fmaf(v1.x, i1, ax); ay = fmaf(v1.y, i1, ay);
        ax = fmaf(v2.x, i2, ax); ay = fmaf(v2.y, i2, ay);
        ax = fmaf(v3.x, i3, ax); ay = fmaf(v3.y, i3, ay);
    }
    for (; e < end; e++) {
        unsigned p = g_packed[e];
        float inv = __shfl_sync(0xffffffffu, inv8, p >> 16);
        float2 v = *(const float2*)&g_H[(size_t)(p & 0xffff) * 512 + (p >> 16) * 64 + lane * 2];
        ax = fmaf(v.x, inv, ax);
        ay = fmaf(v.y, inv, ay);
    }

    const float* base = (sel == 1) ? g_h1 : g_h2;
    float2 b = *(const float2*)&base[(size_t)gw * 64 + lane * 2];
    float o0 = b.x + ax, o1 = b.y + ay;
    o0 = o0 > 0.f ? o0 : 0.f;
    o1 = o1 > 0.f ? o1 : 0.f;
    if (sel == 1) {
        ((__nv_bfloat162*)g_ahi)[gw * 32 + lane] =
            __nv_bfloat162(__float2bfloat16(o0), __float2bfloat16(o1));
    } else {
        *(float2*)&g_h2[(size_t)gw * 64 + lane * 2] = make_float2(o0, o1);
    }
}

// ---------------- final: logits = h2 @ Wl + bl, then log_softmax ----------------
__global__ void __launch_bounds__(256)
final_kernel(const float* __restrict__ Wl, const float* __restrict__ bl,
             float* __restrict__ out) {
    __shared__ float sW[64 * 40];
    __shared__ float sb[40];
    __shared__ float srow[8][64];
    int t = threadIdx.x;
    for (int i = t; i < 64 * 40; i += 256) sW[i] = Wl[i];
    if (t < 40) sb[t] = bl[t];
    __syncthreads();

    int warp = t >> 5, lane = t & 31;
    int n = blockIdx.x * 8 + warp;
    if (n < NN) {
        srow[warp][lane]      = g_h2[(size_t)n * 64 + lane];
        srow[warp][lane + 32] = g_h2[(size_t)n * 64 + 32 + lane];
    }
    __syncwarp();

    float v1 = -1e30f, v2 = -1e30f;
    if (n < NN) {
        float d = sb[lane];
        #pragma unroll
        for (int k = 0; k < 64; k++) d += srow[warp][k] * sW[k * 40 + lane];
        v1 = d;
        if (lane < 8) {
            float d2 = sb[lane + 32];
            #pragma unroll
            for (int k = 0; k < 64; k++) d2 += srow[warp][k] * sW[k * 40 + lane + 32];
            v2 = d2;
        }
    }
    float m = fmaxf(v1, v2);
    #pragma unroll
    for (int o = 16; o > 0; o >>= 1) m = fmaxf(m, __shfl_xor_sync(0xffffffffu, m, o));
    float e1 = __expf(v1 - m);
    float e2 = (lane < 8) ? __expf(v2 - m) : 0.f;
    float s = e1 + e2;
    #pragma unroll
    for (int o = 16; o > 0; o >>= 1) s += __shfl_xor_sync(0xffffffffu, s, o);
    float lse = m + __logf(s);
    if (n < NN) {
        out[(size_t)n * 40 + lane] = v1 - lse;
        if (lane < 8) out[(size_t)n * 40 + 32 + lane] = v2 - lse;
    }
}

// ---------------- launch ---------------------------------------------------------
extern "C" void kernel_launch(void* const* d_in, const int* in_sizes, int n_in,
                              void* d_out, int out_size) {
    const float* x     = (const float*)d_in[0];
    const void*  ei    = d_in[1];
    const void*  et    = d_in[2];
    const float* W1    = (const float*)d_in[3];
    const float* root1 = (const float*)d_in[4];
    const float* b1    = (const float*)d_in[5];
    const float* W2    = (const float*)d_in[6];
    const float* root2 = (const float*)d_in[7];
    const float* b2    = (const float*)d_in[8];
    const float* Wl    = (const float*)d_in[9];
    const float* bl    = (const float*)d_in[10];
    float*       out   = (float*)d_out;

    bf16 *xhi, *ahi;
    cudaGetSymbolAddress((void**)&xhi, g_xhi);
    cudaGetSymbolAddress((void**)&ahi, g_ahi);

    // CSR build + conversions
    zero_detect_kernel<<<(NN * RR + 255) / 256, 256>>>((const unsigned*)ei,
                                                       (const unsigned*)et);
    cvtw_kernel<<<(WT_F2 + 255) / 256, 256>>>(W1, root1, W2, root2);
    cvtx_kernel<<<(NN * 128 / 2 + 255) / 256, 256>>>(x, NN * 128 / 2);
    hist_kernel<<<(EE + 255) / 256, 256>>>(ei, et);
    blocksum_inv_kernel<<<(NN * RR + 255) / 256, 256>>>();
    scanb_kernel<<<1, 256>>>();
    offsets_kernel<<<SCAN_BLOCKS, 256>>>();
    scatter_kernel<<<(EE + 255) / 256, 256>>>(ei, et);

    dim3 g9((NN + 127) / 128, 9);

    // layer 1
    tgemm_kernel<128><<<g9, 256>>>(xhi, b1, 0, 1);
    agg_kernel<<<(NN * 32 + 255) / 256, 256>>>(1);     // -> g_ahi (bf16)

    // layer 2
    tgemm_kernel<64><<<g9, 256>>>(ahi, b2, W2OFF, 2);
    agg_kernel<<<(NN * 32 + 255) / 256, 256>>>(2);     // -> g_h2 (fp32)

    final_kernel<<<(NN + 7) / 8, 256>>>(Wl, bl, out);
}

// round 6
// speedup vs baseline: 2.1430x; 1.1010x over previous
#include <cuda_runtime.h>
#include <cuda_bf16.h>
#include <cuda_fp16.h>
#include <math.h>

#define NN 50000
#define EE 800000
#define RR 8
#define NR (NN * RR)                     // 400000
#define NB2 ((NR + 255) / 256)           // 1563
#define W2OFF (9 * 128 * 64)

typedef unsigned long long ull;
typedef __nv_bfloat16 bf16;

// ---------------- scratch ----------------------------------------------------
__device__ __half    g_H[(size_t)NN * 512];     // fp16 projections (51 MB, L2-resident)
__device__ float     g_h1[(size_t)NN * 64];
__device__ float     g_h2[(size_t)NN * 64];
__device__ bf16      g_xhi[(size_t)NN * 128];
__device__ bf16      g_ahi[(size_t)NN * 64];
__device__ bf16      g_whi[9 * 128 * 64 + 9 * 64 * 64];
__device__ bf16      g_wlo[9 * 128 * 64 + 9 * 64 * 64];
__device__ int       g_cnt[NR];
__device__ int       g_ptr[NR + 1];
__device__ int       g_cur[NR];
__device__ int       g_bsum[NB2];
__device__ ull       g_stage[EE];               // (key<<32)|src, key = dst*8+rel
__device__ unsigned  g_packed[EE];              // (rel<<16)|src, sorted by (dst,rel)
__device__ int       g_is64_idx;
__device__ int       g_is64_typ;

// ---------------- dtype helpers ------------------------------------------------
__device__ __forceinline__ int load_src(const void* ei, int e) {
    return g_is64_idx ? (int)((const long long*)ei)[e] : ((const int*)ei)[e];
}
__device__ __forceinline__ int load_dst(const void* ei, int e) {
    return g_is64_idx ? (int)((const long long*)ei)[EE + e] : ((const int*)ei)[EE + e];
}
__device__ __forceinline__ int load_rel(const void* et, int e) {
    return g_is64_typ ? (int)((const long long*)et)[e] : ((const int*)et)[e];
}

// ---------------- zero + dtype detect -------------------------------------------
__global__ void zero_detect_kernel(const unsigned* __restrict__ idx,
                                   const unsigned* __restrict__ typ) {
    int i = blockIdx.x * blockDim.x + threadIdx.x;
    if (i < NR) g_cnt[i] = 0;
    if (i == 0) {
        unsigned a = 0, b = 0;
        #pragma unroll
        for (int k = 0; k < 64; k++) { a |= idx[2 * k + 1]; b |= typ[2 * k + 1]; }
        g_is64_idx = (a == 0);
        g_is64_typ = (b == 0);
    }
}

// ---------------- hist + stage decoded edges ------------------------------------
__global__ void hist_stage_kernel(const void* __restrict__ ei,
                                  const void* __restrict__ et) {
    int e = blockIdx.x * blockDim.x + threadIdx.x;
    if (e >= EE) return;
    int src = load_src(ei, e);
    int dst = load_dst(ei, e);
    int rel = load_rel(et, e);
    if ((unsigned)src >= NN || (unsigned)dst >= NN || (unsigned)rel >= RR) {
        g_stage[e] = ~0ull;
        return;
    }
    int key = dst * RR + rel;
    atomicAdd(&g_cnt[key], 1);
    g_stage[e] = ((ull)(unsigned)key << 32) | (unsigned)src;
}

// ---------------- scan over 400k (dst,rel) counts --------------------------------
__global__ void blocksum_kernel() {
    int b = blockIdx.x, t = threadIdx.x, i = b * 256 + t;
    int v = (i < NR) ? g_cnt[i] : 0;
    __shared__ int sh[8];
    int lane = t & 31, wid = t >> 5;
    #pragma unroll
    for (int o = 16; o > 0; o >>= 1) v += __shfl_xor_sync(0xffffffffu, v, o);
    if (lane == 0) sh[wid] = v;
    __syncthreads();
    if (t == 0) {
        int s = 0;
        #pragma unroll
        for (int j = 0; j < 8; j++) s += sh[j];
        g_bsum[b] = s;
    }
}

__global__ void scanb_kernel() {
    __shared__ int ws[32];
    __shared__ int carry;
    int t = threadIdx.x, lane = t & 31, wid = t >> 5;
    if (t == 0) carry = 0;
    __syncthreads();
    for (int base = 0; base < NB2; base += 1024) {
        int i = base + t;
        int v = (i < NB2) ? g_bsum[i] : 0;
        int x = v;
        #pragma unroll
        for (int o = 1; o < 32; o <<= 1) {
            int y = __shfl_up_sync(0xffffffffu, x, o);
            if (lane >= o) x += y;
        }
        if (lane == 31) ws[wid] = x;
        __syncthreads();
        if (wid == 0) {
            int s = ws[lane];
            #pragma unroll
            for (int o = 1; o < 32; o <<= 1) {
                int y = __shfl_up_sync(0xffffffffu, s, o);
                if (lane >= o) s += y;
            }
            ws[lane] = s;
        }
        __syncthreads();
        int woff = (wid > 0) ? ws[wid - 1] : 0;
        int excl = carry + woff + x - v;
        if (i < NB2) g_bsum[i] = excl;
        __syncthreads();
        if (t == 0) carry += ws[31];
        __syncthreads();
    }
    if (t == 0) g_ptr[NR] = carry;
}

__device__ __forceinline__ int block_incl_scan256(int v, int t) {
    __shared__ int ws[8];
    int lane = t & 31, wid = t >> 5;
    int x = v;
    #pragma unroll
    for (int o = 1; o < 32; o <<= 1) {
        int y = __shfl_up_sync(0xffffffffu, x, o);
        if (lane >= o) x += y;
    }
    if (lane == 31) ws[wid] = x;
    __syncthreads();
    if (wid == 0) {
        int s = (lane < 8) ? ws[lane] : 0;
        #pragma unroll
        for (int o = 1; o < 8; o <<= 1) {
            int y = __shfl_up_sync(0xffffffffu, s, o);
            if (lane >= o) s += y;
        }
        if (lane < 8) ws[lane] = s;
    }
    __syncthreads();
    if (wid > 0) x += ws[wid - 1];
    return x;
}

__global__ void offsets_kernel() {
    int b = blockIdx.x, t = threadIdx.x, i = b * 256 + t;
    int v = (i < NR) ? g_cnt[i] : 0;
    int incl = block_incl_scan256(v, t);
    int excl = g_bsum[b] + incl - v;
    if (i < NR) { g_ptr[i] = excl; g_cur[i] = excl; }
}

__global__ void scatter_kernel() {
    int e = blockIdx.x * blockDim.x + threadIdx.x;
    if (e >= EE) return;
    ull s = g_stage[e];
    if (s == ~0ull) return;
    int key = (int)(s >> 32);
    unsigned src = (unsigned)s;
    int pos = atomicAdd(&g_cur[key], 1);
    g_packed[pos] = ((unsigned)(key & 7) << 16) | src;
}

// ---------------- conversions ----------------------------------------------------
#define W1_F2   32768
#define R1_F2   4096
#define W2_F2   16384
#define R2_F2   2048
#define WT_F2   (W1_F2 + R1_F2 + W2_F2 + R2_F2)

__global__ void cvtw_kernel(const float* __restrict__ W1, const float* __restrict__ r1,
                            const float* __restrict__ W2, const float* __restrict__ r2) {
    int i = blockIdx.x * blockDim.x + threadIdx.x;
    if (i >= WT_F2) return;
    const float2* src;
    int off;
    if (i < W1_F2)                      { src = (const float2*)W1; off = i; }
    else if (i < W1_F2 + R1_F2)         { src = (const float2*)r1; off = i - W1_F2; }
    else if (i < W1_F2 + R1_F2 + W2_F2) { src = (const float2*)W2; off = i - W1_F2 - R1_F2; }
    else                                { src = (const float2*)r2; off = i - W1_F2 - R1_F2 - W2_F2; }
    float2 v = src[off];
    bf16 hx = __float2bfloat16(v.x);
    bf16 hy = __float2bfloat16(v.y);
    bf16 lx = __float2bfloat16(v.x - __bfloat162float(hx));
    bf16 ly = __float2bfloat16(v.y - __bfloat162float(hy));
    ((__nv_bfloat162*)g_whi)[i] = __nv_bfloat162(hx, hy);
    ((__nv_bfloat162*)g_wlo)[i] = __nv_bfloat162(lx, ly);
}

__global__ void cvtx_kernel(const float* __restrict__ in, int n2) {
    int i = blockIdx.x * blockDim.x + threadIdx.x;
    if (i >= n2) return;
    float2 v = ((const float2*)in)[i];
    ((__nv_bfloat162*)g_xhi)[i] =
        __nv_bfloat162(__float2bfloat16(v.x), __float2bfloat16(v.y));
}

// ---------------- tensor-core helpers ------------------------------------------
__device__ __forceinline__ unsigned smem_u32(const void* p) {
    return (unsigned)__cvta_generic_to_shared(p);
}
__device__ __forceinline__ void ldsm4(unsigned& r0, unsigned& r1, unsigned& r2,
                                      unsigned& r3, unsigned addr) {
    asm volatile("ldmatrix.sync.aligned.m8n8.x4.shared.b16 {%0,%1,%2,%3}, [%4];"
                 : "=r"(r0), "=r"(r1), "=r"(r2), "=r"(r3) : "r"(addr));
}
__device__ __forceinline__ void ldsm4t(unsigned& r0, unsigned& r1, unsigned& r2,
                                       unsigned& r3, unsigned addr) {
    asm volatile("ldmatrix.sync.aligned.m8n8.x4.trans.shared.b16 {%0,%1,%2,%3}, [%4];"
                 : "=r"(r0), "=r"(r1), "=r"(r2), "=r"(r3) : "r"(addr));
}
__device__ __forceinline__ void mma16816(float* d, unsigned a0, unsigned a1,
                                         unsigned a2, unsigned a3,
                                         unsigned b0, unsigned b1) {
    asm volatile(
        "mma.sync.aligned.m16n8k16.row.col.f32.bf16.bf16.f32 "
        "{%0,%1,%2,%3},{%4,%5,%6,%7},{%8,%9},{%0,%1,%2,%3};"
        : "+f"(d[0]), "+f"(d[1]), "+f"(d[2]), "+f"(d[3])
        : "r"(a0), "r"(a1), "r"(a2), "r"(a3), "r"(b0), "r"(b1));
}

// ---------------- tensor GEMM: C[128 x 64] per block, 2-mma split-B -------------
template <int K>
__global__ void __launch_bounds__(256)
tgemm_kernel(const bf16* __restrict__ Ahi, const float* __restrict__ bias,
             int woff, int layer) {
    __shared__ bf16 sA[128 * 40];
    __shared__ bf16 sBhi[32 * 72], sBlo[32 * 72];

    int tid = threadIdx.x, warp = tid >> 5, lane = tid & 31;
    int m0 = blockIdx.x * 128, rel = blockIdx.y;

    const bf16* Whi = g_whi + woff + (size_t)rel * K * 64;
    const bf16* Wlo = g_wlo + woff + (size_t)rel * K * 64;

    float acc[8][4];
    #pragma unroll
    for (int j = 0; j < 8; j++)
        #pragma unroll
        for (int i = 0; i < 4; i++) acc[j][i] = 0.f;

    const uint4 z4 = make_uint4(0, 0, 0, 0);

    for (int kt = 0; kt < K; kt += 32) {
        __syncthreads();
        #pragma unroll
        for (int i = 0; i < 2; i++) {
            int seg = tid + i * 256;
            int row = seg >> 2, s = seg & 3;
            int gr = m0 + row;
            uint4 vh = z4;
            if (gr < NN) vh = *(const uint4*)&Ahi[(size_t)gr * K + kt + s * 8];
            *(uint4*)&sA[row * 40 + s * 8] = vh;
        }
        {
            int row = tid >> 3, s = tid & 7;
            *(uint4*)&sBhi[row * 72 + s * 8] = *(const uint4*)&Whi[(size_t)(kt + row) * 64 + s * 8];
            *(uint4*)&sBlo[row * 72 + s * 8] = *(const uint4*)&Wlo[(size_t)(kt + row) * 64 + s * 8];
        }
        __syncthreads();

        #pragma unroll
        for (int ks = 0; ks < 32; ks += 16) {
            unsigned ah[4];
            unsigned aoff = (warp * 16 + (lane & 15)) * 40 + ks + (lane >> 4) * 8;
            ldsm4(ah[0], ah[1], ah[2], ah[3], smem_u32(&sA[aoff]));
            #pragma unroll
            for (int jj = 0; jj < 4; jj++) {
                int g = lane >> 3;
                int brow = ks + (lane & 7) + (g & 1) * 8;
                int bcol = jj * 16 + (g >> 1) * 8;
                unsigned bh[4], bl[4];
                ldsm4t(bh[0], bh[1], bh[2], bh[3], smem_u32(&sBhi[brow * 72 + bcol]));
                ldsm4t(bl[0], bl[1], bl[2], bl[3], smem_u32(&sBlo[brow * 72 + bcol]));
                mma16816(acc[2 * jj],     ah[0], ah[1], ah[2], ah[3], bh[0], bh[1]);
                mma16816(acc[2 * jj],     ah[0], ah[1], ah[2], ah[3], bl[0], bl[1]);
                mma16816(acc[2 * jj + 1], ah[0], ah[1], ah[2], ah[3], bh[2], bh[3]);
                mma16816(acc[2 * jj + 1], ah[0], ah[1], ah[2], ah[3], bl[2], bl[3]);
            }
        }
    }

    int row = m0 + warp * 16 + (lane >> 2);
    int cb  = (lane & 3) * 2;
    if (rel < 8) {
        // per-relation projection -> fp16 H table
        #pragma unroll
        for (int j = 0; j < 8; j++) {
            int col = rel * 64 + j * 8 + cb;
            if (row < NN)
                *(__half2*)&g_H[(size_t)row * 512 + col] =
                    __floats2half2_rn(acc[j][0], acc[j][1]);
            if (row + 8 < NN)
                *(__half2*)&g_H[(size_t)(row + 8) * 512 + col] =
                    __floats2half2_rn(acc[j][2], acc[j][3]);
        }
    } else {
        float* C = (layer == 1) ? g_h1 : g_h2;
        #pragma unroll
        for (int j = 0; j < 8; j++) {
            int col = j * 8 + cb;
            float b0 = bias[col], b1 = bias[col + 1];
            if (row < NN)
                *(float2*)&C[(size_t)row * 64 + col] =
                    make_float2(acc[j][0] + b0, acc[j][1] + b1);
            if (row + 8 < NN)
                *(float2*)&C[(size_t)(row + 8) * 64 + col] =
                    make_float2(acc[j][2] + b0, acc[j][3] + b1);
        }
    }
}

// ---------------- aggregation: warp per node, MLP-4 fp16 gather -----------------
__global__ void agg_kernel(int sel) {
    int gw   = (blockIdx.x * blockDim.x + threadIdx.x) >> 5;
    int lane = threadIdx.x & 31;
    if (gw >= NN) return;

    int p0 = 0, p1 = 0;
    if (lane < 8) {
        p0 = g_ptr[gw * RR + lane];
        p1 = g_ptr[gw * RR + lane + 1];
    }
    float inv8 = (lane < 8) ? 1.f / (float)max(p1 - p0, 1) : 0.f;
    int beg = __shfl_sync(0xffffffffu, p0, 0);
    int end = __shfl_sync(0xffffffffu, p1, 7);

    float ax = 0.f, ay = 0.f;
    int e = beg;
    for (; e + 4 <= end; e += 4) {
        unsigned q0 = g_packed[e],     q1 = g_packed[e + 1];
        unsigned q2 = g_packed[e + 2], q3 = g_packed[e + 3];
        __half2 v0 = *(const __half2*)&g_H[(size_t)(q0 & 0xffff) * 512 + (q0 >> 16) * 64 + lane * 2];
        __half2 v1 = *(const __half2*)&g_H[(size_t)(q1 & 0xffff) * 512 + (q1 >> 16) * 64 + lane * 2];
        __half2 v2 = *(const __half2*)&g_H[(size_t)(q2 & 0xffff) * 512 + (q2 >> 16) * 64 + lane * 2];
        __half2 v3 = *(const __half2*)&g_H[(size_t)(q3 & 0xffff) * 512 + (q3 >> 16) * 64 + lane * 2];
        float i0 = __shfl_sync(0xffffffffu, inv8, q0 >> 16);
        float i1 = __shfl_sync(0xffffffffu, inv8, q1 >> 16);
        float i2 = __shfl_sync(0xffffffffu, inv8, q2 >> 16);
        float i3 = __shfl_sync(0xffffffffu, inv8, q3 >> 16);
        float2 f0 = __half22float2(v0), f1 = __half22float2(v1);
        float2 f2 = __half22float2(v2), f3 = __half22float2(v3);
        ax = fmaf(f0.x, i0, ax); ay = fmaf(f0.y, i0, ay);
        ax = fmaf(f1.x, i1, ax); ay = fmaf(f1.y, i1, ay);
        ax = fmaf(f2.x, i2, ax); ay = fmaf(f2.y, i2, ay);
        ax = fmaf(f3.x, i3, ax); ay = fmaf(f3.y, i3, ay);
    }
    for (; e < end; e++) {
        unsigned q = g_packed[e];
        float inv = __shfl_sync(0xffffffffu, inv8, q >> 16);
        __half2 v = *(const __half2*)&g_H[(size_t)(q & 0xffff) * 512 + (q >> 16) * 64 + lane * 2];
        float2 f = __half22float2(v);
        ax = fmaf(f.x, inv, ax);
        ay = fmaf(f.y, inv, ay);
    }

    const float* base = (sel == 1) ? g_h1 : g_h2;
    float2 b = *(const float2*)&base[(size_t)gw * 64 + lane * 2];
    float o0 = b.x + ax, o1 = b.y + ay;
    o0 = o0 > 0.f ? o0 : 0.f;
    o1 = o1 > 0.f ? o1 : 0.f;
    if (sel == 1) {
        ((__nv_bfloat162*)g_ahi)[gw * 32 + lane] =
            __nv_bfloat162(__float2bfloat16(o0), __float2bfloat16(o1));
    } else {
        *(float2*)&g_h2[(size_t)gw * 64 + lane * 2] = make_float2(o0, o1);
    }
}

// ---------------- final: logits = h2 @ Wl + bl, then log_softmax ----------------
__global__ void __launch_bounds__(256)
final_kernel(const float* __restrict__ Wl, const float* __restrict__ bl,
             float* __restrict__ out) {
    __shared__ float sW[64 * 40];
    __shared__ float sb[40];
    __shared__ float srow[8][64];
    int t = threadIdx.x;
    for (int i = t; i < 64 * 40; i += 256) sW[i] = Wl[i];
    if (t < 40) sb[t] = bl[t];
    __syncthreads();

    int warp = t >> 5, lane = t & 31;
    int n = blockIdx.x * 8 + warp;
    if (n < NN) {
        srow[warp][lane]      = g_h2[(size_t)n * 64 + lane];
        srow[warp][lane + 32] = g_h2[(size_t)n * 64 + 32 + lane];
    }
    __syncwarp();

    float v1 = -1e30f, v2 = -1e30f;
    if (n < NN) {
        float d = sb[lane];
        #pragma unroll
        for (int k = 0; k < 64; k++) d += srow[warp][k] * sW[k * 40 + lane];
        v1 = d;
        if (lane < 8) {
            float d2 = sb[lane + 32];
            #pragma unroll
            for (int k = 0; k < 64; k++) d2 += srow[warp][k] * sW[k * 40 + lane + 32];
            v2 = d2;
        }
    }
    float m = fmaxf(v1, v2);
    #pragma unroll
    for (int o = 16; o > 0; o >>= 1) m = fmaxf(m, __shfl_xor_sync(0xffffffffu, m, o));
    float e1 = __expf(v1 - m);
    float e2 = (lane < 8) ? __expf(v2 - m) : 0.f;
    float s = e1 + e2;
    #pragma unroll
    for (int o = 16; o > 0; o >>= 1) s += __shfl_xor_sync(0xffffffffu, s, o);
    float lse = m + __logf(s);
    if (n < NN) {
        out[(size_t)n * 40 + lane] = v1 - lse;
        if (lane < 8) out[(size_t)n * 40 + 32 + lane] = v2 - lse;
    }
}

// ---------------- launch ---------------------------------------------------------
extern "C" void kernel_launch(void* const* d_in, const int* in_sizes, int n_in,
                              void* d_out, int out_size) {
    const float* x     = (const float*)d_in[0];
    const void*  ei    = d_in[1];
    const void*  et    = d_in[2];
    const float* W1    = (const float*)d_in[3];
    const float* root1 = (const float*)d_in[4];
    const float* b1    = (const float*)d_in[5];
    const float* W2    = (const float*)d_in[6];
    const float* root2 = (const float*)d_in[7];
    const float* b2    = (const float*)d_in[8];
    const float* Wl    = (const float*)d_in[9];
    const float* bl    = (const float*)d_in[10];
    float*       out   = (float*)d_out;

    bf16 *xhi, *ahi;
    cudaGetSymbolAddress((void**)&xhi, g_xhi);
    cudaGetSymbolAddress((void**)&ahi, g_ahi);

    // CSR build + conversions
    zero_detect_kernel<<<NB2, 256>>>((const unsigned*)ei, (const unsigned*)et);
    cvtw_kernel<<<(WT_F2 + 255) / 256, 256>>>(W1, root1, W2, root2);
    cvtx_kernel<<<(NN * 128 / 2 + 255) / 256, 256>>>(x, NN * 128 / 2);
    hist_stage_kernel<<<(EE + 255) / 256, 256>>>(ei, et);
    blocksum_kernel<<<NB2, 256>>>();
    scanb_kernel<<<1, 1024>>>();
    offsets_kernel<<<NB2, 256>>>();
    scatter_kernel<<<(EE + 255) / 256, 256>>>();

    dim3 g9((NN + 127) / 128, 9);

    // layer 1
    tgemm_kernel<128><<<g9, 256>>>(xhi, b1, 0, 1);
    agg_kernel<<<(NN * 32 + 255) / 256, 256>>>(1);     // -> g_ahi (bf16)

    // layer 2
    tgemm_kernel<64><<<g9, 256>>>(ahi, b2, W2OFF, 2);
    agg_kernel<<<(NN * 32 + 255) / 256, 256>>>(2);     // -> g_h2 (fp32)

    final_kernel<<<(NN + 7) / 8, 256>>>(Wl, bl, out);
}

// round 7
// speedup vs baseline: 2.2216x; 1.0367x over previous
#include <cuda_runtime.h>
#include <cuda_bf16.h>
#include <cuda_fp16.h>
#include <math.h>

#define NN 50000
#define EE 800000
#define RR 8
#define NR (NN * RR)                     // 400000
#define NB2 ((NR + 255) / 256)           // 1563
#define W2OFF (9 * 128 * 64)

typedef unsigned long long ull;
typedef __nv_bfloat16 bf16;

// ---------------- scratch ----------------------------------------------------
__device__ __half    g_H[(size_t)NN * 512];     // fp16 projections (51 MB)
__device__ float     g_h1[(size_t)NN * 64];
__device__ float     g_h2[(size_t)NN * 64];
__device__ bf16      g_xhi[(size_t)NN * 128];
__device__ bf16      g_ahi[(size_t)NN * 64];
__device__ bf16      g_whi[9 * 128 * 64 + 9 * 64 * 64];
__device__ bf16      g_wlo[9 * 128 * 64 + 9 * 64 * 64];
__device__ int       g_cnt[NR];
__device__ int       g_ptr[NR + 1];
__device__ int       g_cur[NR];
__device__ int       g_bsum[NB2];
__device__ ull       g_stage[EE];               // (key<<32)|src, key = dst*8+rel
__device__ unsigned  g_packed[EE];              // (rel<<16)|src, sorted by (dst,rel)
__device__ int       g_is64_idx;
__device__ int       g_is64_typ;

// ---------------- dtype helpers ------------------------------------------------
__device__ __forceinline__ int load_src(const void* ei, int e) {
    return g_is64_idx ? (int)((const long long*)ei)[e] : ((const int*)ei)[e];
}
__device__ __forceinline__ int load_dst(const void* ei, int e) {
    return g_is64_idx ? (int)((const long long*)ei)[EE + e] : ((const int*)ei)[EE + e];
}
__device__ __forceinline__ int load_rel(const void* et, int e) {
    return g_is64_typ ? (int)((const long long*)et)[e] : ((const int*)et)[e];
}

// ---------------- fused prep: zero counts + dtype detect + weight/X convert -----
#define W1_F2   32768
#define R1_F2   4096
#define W2_F2   16384
#define R2_F2   2048
#define WT_F2   (W1_F2 + R1_F2 + W2_F2 + R2_F2)   // 55296
#define X_F2    (NN * 128 / 2)                    // 3200000
#define PREP_MAX X_F2

__global__ void prep_kernel(const unsigned* __restrict__ idx,
                            const unsigned* __restrict__ typ,
                            const float* __restrict__ x,
                            const float* __restrict__ W1, const float* __restrict__ r1,
                            const float* __restrict__ W2, const float* __restrict__ r2) {
    int i = blockIdx.x * blockDim.x + threadIdx.x;
    if (i == 0) {
        unsigned a = 0, b = 0;
        #pragma unroll
        for (int k = 0; k < 64; k++) { a |= idx[2 * k + 1]; b |= typ[2 * k + 1]; }
        g_is64_idx = (a == 0);
        g_is64_typ = (b == 0);
    }
    if (i < NR) g_cnt[i] = 0;
    if (i < WT_F2) {
        const float2* src;
        int off;
        if (i < W1_F2)                      { src = (const float2*)W1; off = i; }
        else if (i < W1_F2 + R1_F2)         { src = (const float2*)r1; off = i - W1_F2; }
        else if (i < W1_F2 + R1_F2 + W2_F2) { src = (const float2*)W2; off = i - W1_F2 - R1_F2; }
        else                                { src = (const float2*)r2; off = i - W1_F2 - R1_F2 - W2_F2; }
        float2 v = src[off];
        bf16 hx = __float2bfloat16(v.x);
        bf16 hy = __float2bfloat16(v.y);
        bf16 lx = __float2bfloat16(v.x - __bfloat162float(hx));
        bf16 ly = __float2bfloat16(v.y - __bfloat162float(hy));
        ((__nv_bfloat162*)g_whi)[i] = __nv_bfloat162(hx, hy);
        ((__nv_bfloat162*)g_wlo)[i] = __nv_bfloat162(lx, ly);
    }
    if (i < X_F2) {
        float2 v = ((const float2*)x)[i];
        ((__nv_bfloat162*)g_xhi)[i] =
            __nv_bfloat162(__float2bfloat16(v.x), __float2bfloat16(v.y));
    }
}

// ---------------- hist + stage decoded edges ------------------------------------
__global__ void hist_stage_kernel(const void* __restrict__ ei,
                                  const void* __restrict__ et) {
    int e = blockIdx.x * blockDim.x + threadIdx.x;
    if (e >= EE) return;
    int src = load_src(ei, e);
    int dst = load_dst(ei, e);
    int rel = load_rel(et, e);
    if ((unsigned)src >= NN || (unsigned)dst >= NN || (unsigned)rel >= RR) {
        g_stage[e] = ~0ull;
        return;
    }
    int key = dst * RR + rel;
    atomicAdd(&g_cnt[key], 1);
    g_stage[e] = ((ull)(unsigned)key << 32) | (unsigned)src;
}

// ---------------- scan over 400k (dst,rel) counts --------------------------------
__global__ void blocksum_kernel() {
    int b = blockIdx.x, t = threadIdx.x, i = b * 256 + t;
    int v = (i < NR) ? g_cnt[i] : 0;
    __shared__ int sh[8];
    int lane = t & 31, wid = t >> 5;
    #pragma unroll
    for (int o = 16; o > 0; o >>= 1) v += __shfl_xor_sync(0xffffffffu, v, o);
    if (lane == 0) sh[wid] = v;
    __syncthreads();
    if (t == 0) {
        int s = 0;
        #pragma unroll
        for (int j = 0; j < 8; j++) s += sh[j];
        g_bsum[b] = s;
    }
}

__global__ void scanb_kernel() {
    __shared__ int ws[32];
    __shared__ int carry;
    int t = threadIdx.x, lane = t & 31, wid = t >> 5;
    if (t == 0) carry = 0;
    __syncthreads();
    for (int base = 0; base < NB2; base += 1024) {
        int i = base + t;
        int v = (i < NB2) ? g_bsum[i] : 0;
        int x = v;
        #pragma unroll
        for (int o = 1; o < 32; o <<= 1) {
            int y = __shfl_up_sync(0xffffffffu, x, o);
            if (lane >= o) x += y;
        }
        if (lane == 31) ws[wid] = x;
        __syncthreads();
        if (wid == 0) {
            int s = ws[lane];
            #pragma unroll
            for (int o = 1; o < 32; o <<= 1) {
                int y = __shfl_up_sync(0xffffffffu, s, o);
                if (lane >= o) s += y;
            }
            ws[lane] = s;
        }
        __syncthreads();
        int woff = (wid > 0) ? ws[wid - 1] : 0;
        int excl = carry + woff + x - v;
        if (i < NB2) g_bsum[i] = excl;
        __syncthreads();
        if (t == 0) carry += ws[31];
        __syncthreads();
    }
    if (t == 0) g_ptr[NR] = carry;
}

__device__ __forceinline__ int block_incl_scan256(int v, int t) {
    __shared__ int ws[8];
    int lane = t & 31, wid = t >> 5;
    int x = v;
    #pragma unroll
    for (int o = 1; o < 32; o <<= 1) {
        int y = __shfl_up_sync(0xffffffffu, x, o);
        if (lane >= o) x += y;
    }
    if (lane == 31) ws[wid] = x;
    __syncthreads();
    if (wid == 0) {
        int s = (lane < 8) ? ws[lane] : 0;
        #pragma unroll
        for (int o = 1; o < 8; o <<= 1) {
            int y = __shfl_up_sync(0xffffffffu, s, o);
            if (lane >= o) s += y;
        }
        if (lane < 8) ws[lane] = s;
    }
    __syncthreads();
    if (wid > 0) x += ws[wid - 1];
    return x;
}

__global__ void offsets_kernel() {
    int b = blockIdx.x, t = threadIdx.x, i = b * 256 + t;
    int v = (i < NR) ? g_cnt[i] : 0;
    int incl = block_incl_scan256(v, t);
    int excl = g_bsum[b] + incl - v;
    if (i < NR) { g_ptr[i] = excl; g_cur[i] = excl; }
}

__global__ void scatter_kernel() {
    int e = blockIdx.x * blockDim.x + threadIdx.x;
    if (e >= EE) return;
    ull s = g_stage[e];
    if (s == ~0ull) return;
    int key = (int)(s >> 32);
    unsigned src = (unsigned)s;
    int pos = atomicAdd(&g_cur[key], 1);
    g_packed[pos] = ((unsigned)(key & 7) << 16) | src;
}

// ---------------- tensor-core helpers ------------------------------------------
__device__ __forceinline__ unsigned smem_u32(const void* p) {
    return (unsigned)__cvta_generic_to_shared(p);
}
__device__ __forceinline__ void ldsm4(unsigned& r0, unsigned& r1, unsigned& r2,
                                      unsigned& r3, unsigned addr) {
    asm volatile("ldmatrix.sync.aligned.m8n8.x4.shared.b16 {%0,%1,%2,%3}, [%4];"
                 : "=r"(r0), "=r"(r1), "=r"(r2), "=r"(r3) : "r"(addr));
}
__device__ __forceinline__ void ldsm4t(unsigned& r0, unsigned& r1, unsigned& r2,
                                       unsigned& r3, unsigned addr) {
    asm volatile("ldmatrix.sync.aligned.m8n8.x4.trans.shared.b16 {%0,%1,%2,%3}, [%4];"
                 : "=r"(r0), "=r"(r1), "=r"(r2), "=r"(r3) : "r"(addr));
}
__device__ __forceinline__ void mma16816(float* d, unsigned a0, unsigned a1,
                                         unsigned a2, unsigned a3,
                                         unsigned b0, unsigned b1) {
    asm volatile(
        "mma.sync.aligned.m16n8k16.row.col.f32.bf16.bf16.f32 "
        "{%0,%1,%2,%3},{%4,%5,%6,%7},{%8,%9},{%0,%1,%2,%3};"
        : "+f"(d[0]), "+f"(d[1]), "+f"(d[2]), "+f"(d[3])
        : "r"(a0), "r"(a1), "r"(a2), "r"(a3), "r"(b0), "r"(b1));
}

// ---------------- tensor GEMM: C[128 x 64] per block, 2-mma split-B -------------
template <int K>
__global__ void __launch_bounds__(256)
tgemm_kernel(const bf16* __restrict__ Ahi, const float* __restrict__ bias,
             int woff, int layer) {
    __shared__ bf16 sA[128 * 40];
    __shared__ bf16 sBhi[32 * 72], sBlo[32 * 72];

    int tid = threadIdx.x, warp = tid >> 5, lane = tid & 31;
    int m0 = blockIdx.x * 128, rel = blockIdx.y;

    const bf16* Whi = g_whi + woff + (size_t)rel * K * 64;
    const bf16* Wlo = g_wlo + woff + (size_t)rel * K * 64;

    float acc[8][4];
    #pragma unroll
    for (int j = 0; j < 8; j++)
        #pragma unroll
        for (int i = 0; i < 4; i++) acc[j][i] = 0.f;

    const uint4 z4 = make_uint4(0, 0, 0, 0);

    for (int kt = 0; kt < K; kt += 32) {
        __syncthreads();
        #pragma unroll
        for (int i = 0; i < 2; i++) {
            int seg = tid + i * 256;
            int row = seg >> 2, s = seg & 3;
            int gr = m0 + row;
            uint4 vh = z4;
            if (gr < NN) vh = *(const uint4*)&Ahi[(size_t)gr * K + kt + s * 8];
            *(uint4*)&sA[row * 40 + s * 8] = vh;
        }
        {
            int row = tid >> 3, s = tid & 7;
            *(uint4*)&sBhi[row * 72 + s * 8] = *(const uint4*)&Whi[(size_t)(kt + row) * 64 + s * 8];
            *(uint4*)&sBlo[row * 72 + s * 8] = *(const uint4*)&Wlo[(size_t)(kt + row) * 64 + s * 8];
        }
        __syncthreads();

        #pragma unroll
        for (int ks = 0; ks < 32; ks += 16) {
            unsigned ah[4];
            unsigned aoff = (warp * 16 + (lane & 15)) * 40 + ks + (lane >> 4) * 8;
            ldsm4(ah[0], ah[1], ah[2], ah[3], smem_u32(&sA[aoff]));
            #pragma unroll
            for (int jj = 0; jj < 4; jj++) {
                int g = lane >> 3;
                int brow = ks + (lane & 7) + (g & 1) * 8;
                int bcol = jj * 16 + (g >> 1) * 8;
                unsigned bh[4], bl[4];
                ldsm4t(bh[0], bh[1], bh[2], bh[3], smem_u32(&sBhi[brow * 72 + bcol]));
                ldsm4t(bl[0], bl[1], bl[2], bl[3], smem_u32(&sBlo[brow * 72 + bcol]));
                mma16816(acc[2 * jj],     ah[0], ah[1], ah[2], ah[3], bh[0], bh[1]);
                mma16816(acc[2 * jj],     ah[0], ah[1], ah[2], ah[3], bl[0], bl[1]);
                mma16816(acc[2 * jj + 1], ah[0], ah[1], ah[2], ah[3], bh[2], bh[3]);
                mma16816(acc[2 * jj + 1], ah[0], ah[1], ah[2], ah[3], bl[2], bl[3]);
            }
        }
    }

    int row = m0 + warp * 16 + (lane >> 2);
    int cb  = (lane & 3) * 2;
    if (rel < 8) {
        #pragma unroll
        for (int j = 0; j < 8; j++) {
            int col = rel * 64 + j * 8 + cb;
            if (row < NN)
                *(__half2*)&g_H[(size_t)row * 512 + col] =
                    __floats2half2_rn(acc[j][0], acc[j][1]);
            if (row + 8 < NN)
                *(__half2*)&g_H[(size_t)(row + 8) * 512 + col] =
                    __floats2half2_rn(acc[j][2], acc[j][3]);
        }
    } else {
        float* C = (layer == 1) ? g_h1 : g_h2;
        #pragma unroll
        for (int j = 0; j < 8; j++) {
            int col = j * 8 + cb;
            float b0 = bias[col], b1 = bias[col + 1];
            if (row < NN)
                *(float2*)&C[(size_t)row * 64 + col] =
                    make_float2(acc[j][0] + b0, acc[j][1] + b1);
            if (row + 8 < NN)
                *(float2*)&C[(size_t)(row + 8) * 64 + col] =
                    make_float2(acc[j][2] + b0, acc[j][3] + b1);
        }
    }
}

// ---------------- aggregation: warp per node, MLP-8 fp16 gather -----------------
__global__ void agg_kernel(int sel) {
    int gw   = (blockIdx.x * blockDim.x + threadIdx.x) >> 5;
    int lane = threadIdx.x & 31;
    if (gw >= NN) return;

    int p0 = 0, p1 = 0;
    if (lane < 8) {
        p0 = g_ptr[gw * RR + lane];
        p1 = g_ptr[gw * RR + lane + 1];
    }
    float inv8 = (lane < 8) ? 1.f / (float)max(p1 - p0, 1) : 0.f;
    int beg = __shfl_sync(0xffffffffu, p0, 0);
    int end = __shfl_sync(0xffffffffu, p1, 7);

    float ax = 0.f, ay = 0.f;
    int e = beg;
    for (; e + 8 <= end; e += 8) {
        unsigned q[8];
        #pragma unroll
        for (int u = 0; u < 8; u++) q[u] = g_packed[e + u];
        __half2 v[8];
        #pragma unroll
        for (int u = 0; u < 8; u++)
            v[u] = *(const __half2*)&g_H[(size_t)(q[u] & 0xffff) * 512 +
                                         (q[u] >> 16) * 64 + lane * 2];
        #pragma unroll
        for (int u = 0; u < 8; u++) {
            float iv = __shfl_sync(0xffffffffu, inv8, q[u] >> 16);
            float2 f = __half22float2(v[u]);
            ax = fmaf(f.x, iv, ax);
            ay = fmaf(f.y, iv, ay);
        }
    }
    for (; e < end; e++) {
        unsigned q = g_packed[e];
        float iv = __shfl_sync(0xffffffffu, inv8, q >> 16);
        __half2 hv = *(const __half2*)&g_H[(size_t)(q & 0xffff) * 512 +
                                           (q >> 16) * 64 + lane * 2];
        float2 f = __half22float2(hv);
        ax = fmaf(f.x, iv, ax);
        ay = fmaf(f.y, iv, ay);
    }

    const float* base = (sel == 1) ? g_h1 : g_h2;
    float2 b = *(const float2*)&base[(size_t)gw * 64 + lane * 2];
    float o0 = b.x + ax, o1 = b.y + ay;
    o0 = o0 > 0.f ? o0 : 0.f;
    o1 = o1 > 0.f ? o1 : 0.f;
    if (sel == 1) {
        ((__nv_bfloat162*)g_ahi)[gw * 32 + lane] =
            __nv_bfloat162(__float2bfloat16(o0), __float2bfloat16(o1));
    } else {
        *(float2*)&g_h2[(size_t)gw * 64 + lane * 2] = make_float2(o0, o1);
    }
}

// ---------------- final: logits = h2 @ Wl + bl, then log_softmax ----------------
__global__ void __launch_bounds__(256)
final_kernel(const float* __restrict__ Wl, const float* __restrict__ bl,
             float* __restrict__ out) {
    __shared__ float sW[64 * 40];
    __shared__ float sb[40];
    __shared__ float srow[8][64];
    int t = threadIdx.x;
    for (int i = t; i < 64 * 40; i += 256) sW[i] = Wl[i];
    if (t < 40) sb[t] = bl[t];
    __syncthreads();

    int warp = t >> 5, lane = t & 31;
    int n = blockIdx.x * 8 + warp;
    if (n < NN) {
        srow[warp][lane]      = g_h2[(size_t)n * 64 + lane];
        srow[warp][lane + 32] = g_h2[(size_t)n * 64 + 32 + lane];
    }
    __syncwarp();

    float v1 = -1e30f, v2 = -1e30f;
    if (n < NN) {
        float d = sb[lane];
        #pragma unroll
        for (int k = 0; k < 64; k++) d += srow[warp][k] * sW[k * 40 + lane];
        v1 = d;
        if (lane < 8) {
            float d2 = sb[lane + 32];
            #pragma unroll
            for (int k = 0; k < 64; k++) d2 += srow[warp][k] * sW[k * 40 + lane + 32];
            v2 = d2;
        }
    }
    float m = fmaxf(v1, v2);
    #pragma unroll
    for (int o = 16; o > 0; o >>= 1) m = fmaxf(m, __shfl_xor_sync(0xffffffffu, m, o));
    float e1 = __expf(v1 - m);
    float e2 = (lane < 8) ? __expf(v2 - m) : 0.f;
    float s = e1 + e2;
    #pragma unroll
    for (int o = 16; o > 0; o >>= 1) s += __shfl_xor_sync(0xffffffffu, s, o);
    float lse = m + __logf(s);
    if (n < NN) {
        out[(size_t)n * 40 + lane] = v1 - lse;
        if (lane < 8) out[(size_t)n * 40 + 32 + lane] = v2 - lse;
    }
}

// ---------------- launch ---------------------------------------------------------
extern "C" void kernel_launch(void* const* d_in, const int* in_sizes, int n_in,
                              void* d_out, int out_size) {
    const float* x     = (const float*)d_in[0];
    const void*  ei    = d_in[1];
    const void*  et    = d_in[2];
    const float* W1    = (const float*)d_in[3];
    const float* root1 = (const float*)d_in[4];
    const float* b1    = (const float*)d_in[5];
    const float* W2    = (const float*)d_in[6];
    const float* root2 = (const float*)d_in[7];
    const float* b2    = (const float*)d_in[8];
    const float* Wl    = (const float*)d_in[9];
    const float* bl    = (const float*)d_in[10];
    float*       out   = (float*)d_out;

    bf16 *xhi, *ahi;
    cudaGetSymbolAddress((void**)&xhi, g_xhi);
    cudaGetSymbolAddress((void**)&ahi, g_ahi);

    // fused prep (zero + detect + weight/X conversion) + CSR build
    prep_kernel<<<(PREP_MAX + 255) / 256, 256>>>((const unsigned*)ei,
                                                 (const unsigned*)et,
                                                 x, W1, root1, W2, root2);
    hist_stage_kernel<<<(EE + 255) / 256, 256>>>(ei, et);
    blocksum_kernel<<<NB2, 256>>>();
    scanb_kernel<<<1, 1024>>>();
    offsets_kernel<<<NB2, 256>>>();
    scatter_kernel<<<(EE + 255) / 256, 256>>>();

    dim3 g9((NN + 127) / 128, 9);

    // layer 1
    tgemm_kernel<128><<<g9, 256>>>(xhi, b1, 0, 1);
    agg_kernel<<<(NN * 32 + 255) / 256, 256>>>(1);     // -> g_ahi (bf16)

    // layer 2
    tgemm_kernel<64><<<g9, 256>>>(ahi, b2, W2OFF, 2);
    agg_kernel<<<(NN * 32 + 255) / 256, 256>>>(2);     // -> g_h2 (fp32)

    final_kernel<<<(NN + 7) / 8, 256>>>(Wl, bl, out);
}

// round 9
// speedup vs baseline: 2.4697x; 1.1117x over previous
#include <cuda_runtime.h>
#include <cuda_bf16.h>
#include <cuda_fp16.h>
#include <math.h>

#define NN 50000
#define EE 800000
#define RR 8
#define NR (NN * RR)
#define NB2 ((NR + 255) / 256)
#define W2OFF (9 * 128 * 64)

typedef unsigned long long ull;

// ---------------- scratch ----------------------------------------------------
__device__ __half    g_H[(size_t)NN * 512];     // fp16 projections (51 MB)
__device__ float     g_h1[(size_t)NN * 64];
__device__ float     g_h2[(size_t)NN * 64];
__device__ __half    g_xh[(size_t)NN * 128];    // fp16 X
__device__ __half    g_ah[(size_t)NN * 64];     // fp16 h1 (layer-2 A)
__device__ __half    g_wh[9 * 128 * 64 + 9 * 64 * 64];   // fp16 weights [rel][k][n]
__device__ int       g_cnt[NR];
__device__ int       g_ptr[NR + 1];
__device__ int       g_cur[NR];
__device__ int       g_bsum[NB2];
__device__ ull       g_stage[EE];               // (key<<32)|src, key = dst*8+rel
__device__ unsigned  g_packed[EE];              // (rel<<16)|src, sorted by (dst,rel)
__device__ int       g_is64_idx;
__device__ int       g_is64_typ;

// ---------------- dtype helpers ------------------------------------------------
__device__ __forceinline__ int load_src(const void* ei, int e) {
    return g_is64_idx ? (int)((const long long*)ei)[e] : ((const int*)ei)[e];
}
__device__ __forceinline__ int load_dst(const void* ei, int e) {
    return g_is64_idx ? (int)((const long long*)ei)[EE + e] : ((const int*)ei)[EE + e];
}
__device__ __forceinline__ int load_rel(const void* et, int e) {
    return g_is64_typ ? (int)((const long long*)et)[e] : ((const int*)et)[e];
}

// ---------------- fused prep: zero counts + dtype detect + fp16 conversions -----
#define W1_F2   32768     // 8*128*64/2
#define R1_F2   4096
#define W2_F2   16384
#define R2_F2   2048
#define WT_F2   (W1_F2 + R1_F2 + W2_F2 + R2_F2)   // 55296
#define X_F2    (NN * 128 / 2)                    // 3200000
#define PREP_MAX X_F2

__global__ void prep_kernel(const unsigned* __restrict__ idx,
                            const unsigned* __restrict__ typ,
                            const float* __restrict__ x,
                            const float* __restrict__ W1, const float* __restrict__ r1,
                            const float* __restrict__ W2, const float* __restrict__ r2) {
    int i = blockIdx.x * blockDim.x + threadIdx.x;
    if (i == 0) {
        unsigned a = 0, b = 0;
        #pragma unroll
        for (int k = 0; k < 64; k++) { a |= idx[2 * k + 1]; b |= typ[2 * k + 1]; }
        g_is64_idx = (a == 0);
        g_is64_typ = (b == 0);
    }
    if (i < NR) g_cnt[i] = 0;
    if (i < WT_F2) {
        const float2* src;
        int off;
        if (i < W1_F2)                      { src = (const float2*)W1; off = i; }
        else if (i < W1_F2 + R1_F2)         { src = (const float2*)r1; off = i - W1_F2; }
        else if (i < W1_F2 + R1_F2 + W2_F2) { src = (const float2*)W2; off = i - W1_F2 - R1_F2; }
        else                                { src = (const float2*)r2; off = i - W1_F2 - R1_F2 - W2_F2; }
        float2 v = src[off];
        ((__half2*)g_wh)[i] = __floats2half2_rn(v.x, v.y);
    }
    if (i < X_F2) {
        float2 v = ((const float2*)x)[i];
        ((__half2*)g_xh)[i] = __floats2half2_rn(v.x, v.y);
    }
}

// ---------------- hist + stage decoded edges ------------------------------------
__global__ void hist_stage_kernel(const void* __restrict__ ei,
                                  const void* __restrict__ et) {
    int e = blockIdx.x * blockDim.x + threadIdx.x;
    if (e >= EE) return;
    int src = load_src(ei, e);
    int dst = load_dst(ei, e);
    int rel = load_rel(et, e);
    if ((unsigned)src >= NN || (unsigned)dst >= NN || (unsigned)rel >= RR) {
        g_stage[e] = ~0ull;
        return;
    }
    int key = dst * RR + rel;
    atomicAdd(&g_cnt[key], 1);
    g_stage[e] = ((ull)(unsigned)key << 32) | (unsigned)src;
}

// ---------------- scan over 400k (dst,rel) counts --------------------------------
__global__ void blocksum_kernel() {
    int b = blockIdx.x, t = threadIdx.x, i = b * 256 + t;
    int v = (i < NR) ? g_cnt[i] : 0;
    __shared__ int sh[8];
    int lane = t & 31, wid = t >> 5;
    #pragma unroll
    for (int o = 16; o > 0; o >>= 1) v += __shfl_xor_sync(0xffffffffu, v, o);
    if (lane == 0) sh[wid] = v;
    __syncthreads();
    if (t == 0) {
        int s = 0;
        #pragma unroll
        for (int j = 0; j < 8; j++) s += sh[j];
        g_bsum[b] = s;
    }
}

__global__ void scanb_kernel() {
    __shared__ int ws[32];
    __shared__ int carry;
    int t = threadIdx.x, lane = t & 31, wid = t >> 5;
    if (t == 0) carry = 0;
    __syncthreads();
    for (int base = 0; base < NB2; base += 1024) {
        int i = base + t;
        int v = (i < NB2) ? g_bsum[i] : 0;
        int x = v;
        #pragma unroll
        for (int o = 1; o < 32; o <<= 1) {
            int y = __shfl_up_sync(0xffffffffu, x, o);
            if (lane >= o) x += y;
        }
        if (lane == 31) ws[wid] = x;
        __syncthreads();
        if (wid == 0) {
            int s = ws[lane];
            #pragma unroll
            for (int o = 1; o < 32; o <<= 1) {
                int y = __shfl_up_sync(0xffffffffu, s, o);
                if (lane >= o) s += y;
            }
            ws[lane] = s;
        }
        __syncthreads();
        int woff = (wid > 0) ? ws[wid - 1] : 0;
        int excl = carry + woff + x - v;
        if (i < NB2) g_bsum[i] = excl;
        __syncthreads();
        if (t == 0) carry += ws[31];
        __syncthreads();
    }
    if (t == 0) g_ptr[NR] = carry;
}

__device__ __forceinline__ int block_incl_scan256(int v, int t) {
    __shared__ int ws[8];
    int lane = t & 31, wid = t >> 5;
    int x = v;
    #pragma unroll
    for (int o = 1; o < 32; o <<= 1) {
        int y = __shfl_up_sync(0xffffffffu, x, o);
        if (lane >= o) x += y;
    }
    if (lane == 31) ws[wid] = x;
    __syncthreads();
    if (wid == 0) {
        int s = (lane < 8) ? ws[lane] : 0;
        #pragma unroll
        for (int o = 1; o < 8; o <<= 1) {
            int y = __shfl_up_sync(0xffffffffu, s, o);
            if (lane >= o) s += y;
        }
        if (lane < 8) ws[lane] = s;
    }
    __syncthreads();
    if (wid > 0) x += ws[wid - 1];
    return x;
}

__global__ void offsets_kernel() {
    int b = blockIdx.x, t = threadIdx.x, i = b * 256 + t;
    int v = (i < NR) ? g_cnt[i] : 0;
    int incl = block_incl_scan256(v, t);
    int excl = g_bsum[b] + incl - v;
    if (i < NR) { g_ptr[i] = excl; g_cur[i] = excl; }
}

__global__ void scatter_kernel() {
    int e = blockIdx.x * blockDim.x + threadIdx.x;
    if (e >= EE) return;
    ull s = g_stage[e];
    if (s == ~0ull) return;
    int key = (int)(s >> 32);
    unsigned src = (unsigned)s;
    int pos = atomicAdd(&g_cur[key], 1);
    g_packed[pos] = ((unsigned)(key & 7) << 16) | src;
}

// ---------------- tensor-core helpers ------------------------------------------
__device__ __forceinline__ unsigned smem_u32(const void* p) {
    return (unsigned)__cvta_generic_to_shared(p);
}
__device__ __forceinline__ void ldsm4(unsigned& r0, unsigned& r1, unsigned& r2,
                                      unsigned& r3, unsigned addr) {
    asm volatile("ldmatrix.sync.aligned.m8n8.x4.shared.b16 {%0,%1,%2,%3}, [%4];"
                 : "=r"(r0), "=r"(r1), "=r"(r2), "=r"(r3) : "r"(addr));
}
__device__ __forceinline__ void ldsm4t(unsigned& r0, unsigned& r1, unsigned& r2,
                                       unsigned& r3, unsigned addr) {
    asm volatile("ldmatrix.sync.aligned.m8n8.x4.trans.shared.b16 {%0,%1,%2,%3}, [%4];"
                 : "=r"(r0), "=r"(r1), "=r"(r2), "=r"(r3) : "r"(addr));
}
__device__ __forceinline__ void mma16816h(float* d, unsigned a0, unsigned a1,
                                          unsigned a2, unsigned a3,
                                          unsigned b0, unsigned b1) {
    asm volatile(
        "mma.sync.aligned.m16n8k16.row.col.f32.f16.f16.f32 "
        "{%0,%1,%2,%3},{%4,%5,%6,%7},{%8,%9},{%0,%1,%2,%3};"
        : "+f"(d[0]), "+f"(d[1]), "+f"(d[2]), "+f"(d[3])
        : "r"(a0), "r"(a1), "r"(a2), "r"(a3), "r"(b0), "r"(b1));
}

// ---------------- fp16 tensor GEMM: C[128 x 64] per block -----------------------
// grid.y == 9: y<8 -> g_H slice (fp16, ldc 512), y==8 -> root into g_h1/g_h2
template <int K>
__global__ void __launch_bounds__(256)
tgemm_kernel(const __half* __restrict__ A, const float* __restrict__ bias,
             int woff, int layer) {
    __shared__ __half sA[128 * 40];    // row stride 40 halves (80 B)
    __shared__ __half sB[32 * 72];     // row stride 72 halves (144 B)

    int tid = threadIdx.x, warp = tid >> 5, lane = tid & 31;
    int m0 = blockIdx.x * 128, rel = blockIdx.y;

    const __half* W = g_wh + woff + (size_t)rel * K * 64;

    float acc[8][4];
    #pragma unroll
    for (int j = 0; j < 8; j++)
        #pragma unroll
        for (int i = 0; i < 4; i++) acc[j][i] = 0.f;

    const uint4 z4 = make_uint4(0, 0, 0, 0);

    for (int kt = 0; kt < K; kt += 32) {
        __syncthreads();
        #pragma unroll
        for (int i = 0; i < 2; i++) {
            int seg = tid + i * 256;
            int row = seg >> 2, s = seg & 3;
            int gr = m0 + row;
            uint4 vh = z4;
            if (gr < NN) vh = *(const uint4*)&A[(size_t)gr * K + kt + s * 8];
            *(uint4*)&sA[row * 40 + s * 8] = vh;
        }
        {
            int row = tid >> 3, s = tid & 7;
            *(uint4*)&sB[row * 72 + s * 8] = *(const uint4*)&W[(size_t)(kt + row) * 64 + s * 8];
        }
        __syncthreads();

        #pragma unroll
        for (int ks = 0; ks < 32; ks += 16) {
            unsigned ah[4];
            unsigned aoff = (warp * 16 + (lane & 15)) * 40 + ks + (lane >> 4) * 8;
            ldsm4(ah[0], ah[1], ah[2], ah[3], smem_u32(&sA[aoff]));
            #pragma unroll
            for (int jj = 0; jj < 4; jj++) {
                int g = lane >> 3;
                int brow = ks + (lane & 7) + (g & 1) * 8;
                int bcol = jj * 16 + (g >> 1) * 8;
                unsigned bh[4];
                ldsm4t(bh[0], bh[1], bh[2], bh[3], smem_u32(&sB[brow * 72 + bcol]));
                mma16816h(acc[2 * jj],     ah[0], ah[1], ah[2], ah[3], bh[0], bh[1]);
                mma16816h(acc[2 * jj + 1], ah[0], ah[1], ah[2], ah[3], bh[2], bh[3]);
            }
        }
    }

    int row = m0 + warp * 16 + (lane >> 2);
    int cb  = (lane & 3) * 2;
    if (rel < 8) {
        #pragma unroll
        for (int j = 0; j < 8; j++) {
            int col = rel * 64 + j * 8 + cb;
            if (row < NN)
                *(__half2*)&g_H[(size_t)row * 512 + col] =
                    __floats2half2_rn(acc[j][0], acc[j][1]);
            if (row + 8 < NN)
                *(__half2*)&g_H[(size_t)(row + 8) * 512 + col] =
                    __floats2half2_rn(acc[j][2], acc[j][3]);
        }
    } else {
        float* C = (layer == 1) ? g_h1 : g_h2;
        #pragma unroll
        for (int j = 0; j < 8; j++) {
            int col = j * 8 + cb;
            float b0 = bias[col], b1 = bias[col + 1];
            if (row < NN)
                *(float2*)&C[(size_t)row * 64 + col] =
                    make_float2(acc[j][0] + b0, acc[j][1] + b1);
            if (row + 8 < NN)
                *(float2*)&C[(size_t)(row + 8) * 64 + col] =
                    make_float2(acc[j][2] + b0, acc[j][3] + b1);
        }
    }
}

// ---------------- aggregation: warp per node, MLP-8 fp16 gather -----------------
__global__ void agg_kernel(int sel) {
    int gw   = (blockIdx.x * blockDim.x + threadIdx.x) >> 5;
    int lane = threadIdx.x & 31;
    if (gw >= NN) return;

    int p0 = 0, p1 = 0;
    if (lane < 8) {
        p0 = g_ptr[gw * RR + lane];
        p1 = g_ptr[gw * RR + lane + 1];
    }
    float inv8 = (lane < 8) ? 1.f / (float)max(p1 - p0, 1) : 0.f;
    int beg = __shfl_sync(0xffffffffu, p0, 0);
    int end = __shfl_sync(0xffffffffu, p1, 7);

    float ax = 0.f, ay = 0.f;
    int e = beg;
    for (; e + 8 <= end; e += 8) {
        unsigned q[8];
        #pragma unroll
        for (int u = 0; u < 8; u++) q[u] = g_packed[e + u];
        __half2 v[8];
        #pragma unroll
        for (int u = 0; u < 8; u++)
            v[u] = *(const __half2*)&g_H[(size_t)(q[u] & 0xffff) * 512 +
                                         (q[u] >> 16) * 64 + lane * 2];
        #pragma unroll
        for (int u = 0; u < 8; u++) {
            float iv = __shfl_sync(0xffffffffu, inv8, q[u] >> 16);
            float2 f = __half22float2(v[u]);
            ax = fmaf(f.x, iv, ax);
            ay = fmaf(f.y, iv, ay);
        }
    }
    for (; e < end; e++) {
        unsigned q = g_packed[e];
        float iv = __shfl_sync(0xffffffffu, inv8, q >> 16);
        __half2 hv = *(const __half2*)&g_H[(size_t)(q & 0xffff) * 512 +
                                           (q >> 16) * 64 + lane * 2];
        float2 f = __half22float2(hv);
        ax = fmaf(f.x, iv, ax);
        ay = fmaf(f.y, iv, ay);
    }

    const float* base = (sel == 1) ? g_h1 : g_h2;
    float2 b = *(const float2*)&base[(size_t)gw * 64 + lane * 2];
    float o0 = b.x + ax, o1 = b.y + ay;
    o0 = o0 > 0.f ? o0 : 0.f;
    o1 = o1 > 0.f ? o1 : 0.f;
    if (sel == 1) {
        ((__half2*)g_ah)[gw * 32 + lane] = __floats2half2_rn(o0, o1);
    } else {
        *(float2*)&g_h2[(size_t)gw * 64 + lane * 2] = make_float2(o0, o1);
    }
}

// ---------------- final: logits = h2 @ Wl + bl, then log_softmax ----------------
__global__ void __launch_bounds__(256)
final_kernel(const float* __restrict__ Wl, const float* __restrict__ bl,
             float* __restrict__ out) {
    __shared__ float sW[64 * 40];
    __shared__ float sb[40];
    __shared__ float srow[8][64];
    int t = threadIdx.x;
    for (int i = t; i < 64 * 40; i += 256) sW[i] = Wl[i];
    if (t < 40) sb[t] = bl[t];
    __syncthreads();

    int warp = t >> 5, lane = t & 31;
    int n = blockIdx.x * 8 + warp;
    if (n < NN) {
        srow[warp][lane]      = g_h2[(size_t)n * 64 + lane];
        srow[warp][lane + 32] = g_h2[(size_t)n * 64 + 32 + lane];
    }
    __syncwarp();

    float v1 = -1e30f, v2 = -1e30f;
    if (n < NN) {
        float d = sb[lane];
        #pragma unroll
        for (int k = 0; k < 64; k++) d += srow[warp][k] * sW[k * 40 + lane];
        v1 = d;
        if (lane < 8) {
            float d2 = sb[lane + 32];
            #pragma unroll
            for (int k = 0; k < 64; k++) d2 += srow[warp][k] * sW[k * 40 + lane + 32];
            v2 = d2;
        }
    }
    float m = fmaxf(v1, v2);
    #pragma unroll
    for (int o = 16; o > 0; o >>= 1) m = fmaxf(m, __shfl_xor_sync(0xffffffffu, m, o));
    float e1 = __expf(v1 - m);
    float e2 = (lane < 8) ? __expf(v2 - m) : 0.f;
    float s = e1 + e2;
    #pragma unroll
    for (int o = 16; o > 0; o >>= 1) s += __shfl_xor_sync(0xffffffffu, s, o);
    float lse = m + __logf(s);
    if (n < NN) {
        out[(size_t)n * 40 + lane] = v1 - lse;
        if (lane < 8) out[(size_t)n * 40 + 32 + lane] = v2 - lse;
    }
}

// ---------------- launch ---------------------------------------------------------
extern "C" void kernel_launch(void* const* d_in, const int* in_sizes, int n_in,
                              void* d_out, int out_size) {
    const float* x     = (const float*)d_in[0];
    const void*  ei    = d_in[1];
    const void*  et    = d_in[2];
    const float* W1    = (const float*)d_in[3];
    const float* root1 = (const float*)d_in[4];
    const float* b1    = (const float*)d_in[5];
    const float* W2    = (const float*)d_in[6];
    const float* root2 = (const float*)d_in[7];
    const float* b2    = (const float*)d_in[8];
    const float* Wl    = (const float*)d_in[9];
    const float* bl    = (const float*)d_in[10];
    float*       out   = (float*)d_out;

    __half *xh, *ah;
    cudaGetSymbolAddress((void**)&xh, g_xh);
    cudaGetSymbolAddress((void**)&ah, g_ah);

    // fused prep (zero + detect + fp16 conversions) + CSR build
    prep_kernel<<<(PREP_MAX + 255) / 256, 256>>>((const unsigned*)ei,
                                                 (const unsigned*)et,
                                                 x, W1, root1, W2, root2);
    hist_stage_kernel<<<(EE + 255) / 256, 256>>>(ei, et);
    blocksum_kernel<<<NB2, 256>>>();
    scanb_kernel<<<1, 1024>>>();
    offsets_kernel<<<NB2, 256>>>();
    scatter_kernel<<<(EE + 255) / 256, 256>>>();

    dim3 g9((NN + 127) / 128, 9);

    // layer 1
    tgemm_kernel<128><<<g9, 256>>>(xh, b1, 0, 1);
    agg_kernel<<<(NN * 32 + 255) / 256, 256>>>(1);     // -> g_ah (fp16)

    // layer 2
    tgemm_kernel<64><<<g9, 256>>>(ah, b2, W2OFF, 2);
    agg_kernel<<<(NN * 32 + 255) / 256, 256>>>(2);     // -> g_h2 (fp32)

    final_kernel<<<(NN + 7) / 8, 256>>>(Wl, bl, out);
}